// round 7
// baseline (speedup 1.0000x reference)
#include <cuda_runtime.h>
#include <cuda_bf16.h>
#include <math.h>
#include <cstdint>

// Problem constants
#define BATCH 2
#define SEQ   2048
#define EMBED 2048
#define NH    16
#define NKV   4
#define HD    128
#define FF    5632
#define ROWS  (BATCH*SEQ)          // 4096
#define QKV_N ((NH + 2*NKV)*HD)    // 3072

// ================= scratch (static device globals) =============================
__device__ float g_qkv [ROWS*QKV_N];   // only V region written/used after fusion
__device__ float g_h2  [ROWS*EMBED];
__device__ float g_ff1 [ROWS*FF];
__device__ __nv_bfloat16 g_nhi[ROWS*EMBED], g_nlo[ROWS*EMBED];
__device__ __nv_bfloat16 g_ahi[ROWS*EMBED], g_alo[ROWS*EMBED];
__device__ __nv_bfloat16 g_fhi[ROWS*FF],    g_flo[ROWS*FF];
__device__ __nv_bfloat16 g_qh[ROWS*NH*HD],  g_ql[ROWS*NH*HD];
__device__ __nv_bfloat16 g_kh[ROWS*NKV*HD], g_kl[ROWS*NKV*HD];
__device__ __nv_bfloat16 g_vh[ROWS*NKV*HD], g_vl[ROWS*NKV*HD];   // transposed [b,kh,d,s]
__device__ __nv_bfloat16 g_wqkv_h[QKV_N*EMBED], g_wqkv_l[QKV_N*EMBED];
__device__ __nv_bfloat16 g_wfc_h[EMBED*EMBED],  g_wfc_l[EMBED*EMBED];
__device__ __nv_bfloat16 g_w1_h[FF*EMBED],      g_w1_l[FF*EMBED];
__device__ __nv_bfloat16 g_w2_h[FF*EMBED],      g_w2_l[FF*EMBED];
__device__ __nv_bfloat16 g_w3_h[EMBED*FF],      g_w3_l[EMBED*FF];

// ================= helpers =====================================================
__device__ __forceinline__ float silu_f(float z) { return z / (1.0f + __expf(-z)); }

__device__ __forceinline__ uint32_t smem_u32(const void* p) {
    uint32_t a;
    asm("{ .reg .u64 t; cvta.to.shared.u64 t, %1; cvt.u32.u64 %0, t; }" : "=r"(a) : "l"(p));
    return a;
}
__device__ __forceinline__ void cpa16(uint32_t so, const void* ga) {
    asm volatile("cp.async.cg.shared.global [%0], [%1], 16;\n" :: "r"(so), "l"(ga));
}
__device__ __forceinline__ void ldsm_x4(uint32_t (&r)[4], uint32_t addr) {
    asm volatile("ldmatrix.sync.aligned.m8n8.x4.shared.b16 {%0,%1,%2,%3}, [%4];"
                 : "=r"(r[0]), "=r"(r[1]), "=r"(r[2]), "=r"(r[3]) : "r"(addr));
}
__device__ __forceinline__ void mma_bf16(float (&d)[4], const uint32_t (&a)[4],
                                         uint32_t b0, uint32_t b1) {
    asm volatile(
        "mma.sync.aligned.m16n8k16.row.col.f32.bf16.bf16.f32 "
        "{%0,%1,%2,%3}, {%4,%5,%6,%7}, {%8,%9}, {%0,%1,%2,%3};"
        : "+f"(d[0]), "+f"(d[1]), "+f"(d[2]), "+f"(d[3])
        : "r"(a[0]), "r"(a[1]), "r"(a[2]), "r"(a[3]), "r"(b0), "r"(b1));
}
// pack two fp32 -> bf16x2 (lo arg -> low half, hi arg -> high half)
__device__ __forceinline__ uint32_t packbf(float lo, float hi) {
    uint32_t d;
    asm("cvt.rn.bf16x2.f32 %0, %1, %2;" : "=r"(d) : "f"(hi), "f"(lo));
    return d;
}

__device__ __forceinline__ void store_hl4(__nv_bfloat16* __restrict__ hi,
                                          __nv_bfloat16* __restrict__ lo,
                                          size_t idx, float a, float b, float c, float d)
{
    __nv_bfloat16 h0 = __float2bfloat16(a), h1 = __float2bfloat16(b);
    __nv_bfloat16 h2 = __float2bfloat16(c), h3 = __float2bfloat16(d);
    __nv_bfloat16 l0 = __float2bfloat16(a - __bfloat162float(h0));
    __nv_bfloat16 l1 = __float2bfloat16(b - __bfloat162float(h1));
    __nv_bfloat16 l2 = __float2bfloat16(c - __bfloat162float(h2));
    __nv_bfloat16 l3 = __float2bfloat16(d - __bfloat162float(h3));
    __nv_bfloat162 p;
    p.x = h0; p.y = h1; *(__nv_bfloat162*)(hi + idx)     = p;
    p.x = h2; p.y = h3; *(__nv_bfloat162*)(hi + idx + 2) = p;
    p.x = l0; p.y = l1; *(__nv_bfloat162*)(lo + idx)     = p;
    p.x = l2; p.y = l3; *(__nv_bfloat162*)(lo + idx + 2) = p;
}

__device__ __forceinline__ void store_hl2(__nv_bfloat16* __restrict__ hi,
                                          __nv_bfloat16* __restrict__ lo,
                                          size_t idx, float a, float b)
{
    __nv_bfloat16 h0 = __float2bfloat16(a), h1 = __float2bfloat16(b);
    __nv_bfloat16 l0 = __float2bfloat16(a - __bfloat162float(h0));
    __nv_bfloat16 l1 = __float2bfloat16(b - __bfloat162float(h1));
    __nv_bfloat162 p;
    p.x = h0; p.y = h1; *(__nv_bfloat162*)(hi + idx) = p;
    p.x = l0; p.y = l1; *(__nv_bfloat162*)(lo + idx) = p;
}

// fp32 -> (hi, lo) bf16 split
__global__ __launch_bounds__(256) void cvt_hl(
    const float* __restrict__ src, __nv_bfloat16* __restrict__ hi,
    __nv_bfloat16* __restrict__ lo, int n4)
{
    int i = blockIdx.x * 256 + threadIdx.x;
    if (i >= n4) return;
    float4 v = ((const float4*)src)[i];
    store_hl4(hi, lo, (size_t)i * 4, v.x, v.y, v.z, v.w);
}

// rmsnorm with hi/lo bf16 output
__global__ __launch_bounds__(256) void rmsnorm_hl(
    const float* __restrict__ x, const float* __restrict__ w,
    __nv_bfloat16* __restrict__ hi, __nv_bfloat16* __restrict__ lo)
{
    int row = blockIdx.x;
    const float4* xr = (const float4*)(x + (size_t)row * EMBED);
    int t = threadIdx.x;
    float4 v0 = xr[t];
    float4 v1 = xr[t + 256];
    float ss = v0.x*v0.x + v0.y*v0.y + v0.z*v0.z + v0.w*v0.w
             + v1.x*v1.x + v1.y*v1.y + v1.z*v1.z + v1.w*v1.w;
    #pragma unroll
    for (int m = 16; m; m >>= 1) ss += __shfl_xor_sync(0xffffffffu, ss, m);
    __shared__ float red[8];
    if ((t & 31) == 0) red[t >> 5] = ss;
    __syncthreads();
    float tot = red[0]+red[1]+red[2]+red[3]+red[4]+red[5]+red[6]+red[7];
    float r = rsqrtf(tot * (1.0f/EMBED) + 1e-5f);
    const float4* wr = (const float4*)w;
    float4 w0 = wr[t], w1 = wr[t + 256];
    size_t base = (size_t)row * EMBED;
    store_hl4(hi, lo, base + t*4,        v0.x*r*w0.x, v0.y*r*w0.y, v0.z*r*w0.z, v0.w*r*w0.w);
    store_hl4(hi, lo, base + 1024 + t*4, v1.x*r*w1.x, v1.y*r*w1.y, v1.z*r*w1.z, v1.w*r*w1.w);
}

// ---------------- V: transpose to [b,kh,d,s] + hi/lo split ---------------------
__global__ __launch_bounds__(256) void v_split_t(
    const float* __restrict__ qkv,
    __nv_bfloat16* __restrict__ vh, __nv_bfloat16* __restrict__ vl)
{
    __shared__ float tile[32][33];
    int s0 = blockIdx.x * 32, d0 = blockIdx.y * 32;
    int b  = blockIdx.z >> 2, kh = blockIdx.z & 3;
    int tx = threadIdx.x & 31, ty = threadIdx.x >> 5;   // 32 x 8
    #pragma unroll
    for (int i = 0; i < 4; i++) {
        int s = s0 + ty + i*8;
        tile[ty + i*8][tx] = qkv[(size_t)(b*SEQ + s) * QKV_N + (NH+NKV)*HD + kh*HD + d0 + tx];
    }
    __syncthreads();
    #pragma unroll
    for (int i = 0; i < 4; i++) {
        int d = d0 + ty + i*8;
        float v = tile[tx][ty + i*8];
        size_t o = ((size_t)(b*NKV + kh) * HD + d) * SEQ + s0 + tx;
        __nv_bfloat16 h = __float2bfloat16(v);
        vh[o] = h;
        vl[o] = __float2bfloat16(v - __bfloat162float(h));
    }
}

// ================= HMMA bf16x3 GEMM ============================================
// C[M,N] = A[M,K] @ B[N,K]^T with A,B as (hi,lo) bf16 pairs; 3-product compensation.
// EPI 0: Cf = acc
// EPI 1: Cf = acc + X
// EPI 2: qkv fused: Q/K heads -> RoPE + hi/lo head-major (X = freqs); V -> fp32 Cf
// EPI 3: (Chi,Clo) = split(acc * silu(X))
#define BKC      32
#define RS       40
#define TILE_PB  (128*RS*2)
#define STAGE_B  (4*TILE_PB)
#define NSTAGE   2
#define GEMM_SMEM (NSTAGE*STAGE_B)     // 81920

__device__ __forceinline__ void load_stage(
    uint32_t sb, int stage, int chunk, int tid,
    const __nv_bfloat16* __restrict__ A0, const __nv_bfloat16* __restrict__ A1,
    const __nv_bfloat16* __restrict__ B0, const __nv_bfloat16* __restrict__ B1, int K)
{
    const __nv_bfloat16* mats[4] = {A0, A1, B0, B1};
    uint32_t stage_base = sb + (uint32_t)stage * STAGE_B;
    #pragma unroll
    for (int m = 0; m < 4; m++) {
        const __nv_bfloat16* gp = mats[m] + chunk * BKC;
        uint32_t tb = stage_base + m * TILE_PB;
        #pragma unroll
        for (int it = 0; it < 2; it++) {
            int ch = it * 256 + tid;
            int r  = ch >> 2;
            int cc = ch & 3;
            uint32_t so = tb + (uint32_t)(r * (RS*2) + cc * 16);
            cpa16(so, gp + (size_t)r * K + cc * 8);
        }
    }
}

template<int EPI>
__global__ __launch_bounds__(256, 2) void hmma_gemm(
    const __nv_bfloat16* __restrict__ Ahi, const __nv_bfloat16* __restrict__ Alo,
    const __nv_bfloat16* __restrict__ Bhi, const __nv_bfloat16* __restrict__ Blo,
    float* __restrict__ Cf, const float* __restrict__ X,
    __nv_bfloat16* __restrict__ Chi, __nv_bfloat16* __restrict__ Clo,
    __nv_bfloat16* __restrict__ Qh2, __nv_bfloat16* __restrict__ Ql2,
    __nv_bfloat16* __restrict__ Kh2, __nv_bfloat16* __restrict__ Kl2,
    int M, int N, int K)
{
    extern __shared__ char smem[];
    uint32_t sb = smem_u32(smem);
    const int tid  = threadIdx.x;
    const int wid  = tid >> 5;
    const int lane = tid & 31;
    const int bx = blockIdx.x, by = blockIdx.y;
    const int wm = (wid >> 2) * 64;
    const int wn = (wid & 3) * 32;

    const __nv_bfloat16* A0 = Ahi + (size_t)by * 128 * K;
    const __nv_bfloat16* A1 = Alo + (size_t)by * 128 * K;
    const __nv_bfloat16* B0 = Bhi + (size_t)bx * 128 * K;
    const __nv_bfloat16* B1 = Blo + (size_t)bx * 128 * K;

    float d[4][4][4];
    #pragma unroll
    for (int i = 0; i < 4; i++)
        #pragma unroll
        for (int j = 0; j < 4; j++)
            #pragma unroll
            for (int r = 0; r < 4; r++) d[i][j][r] = 0.0f;

    const int a_row = lane & 15;
    const int a_cb  = (lane >> 4) * 16;
    const int b_row = (lane & 7) | ((lane >> 1) & 8);
    const int b_cb  = ((lane >> 3) & 1) * 16;

    const int NC = K / BKC;

    load_stage(sb, 0, 0, tid, A0, A1, B0, B1, K);
    asm volatile("cp.async.commit_group;\n" ::: "memory");

    for (int c = 0; c < NC; c++) {
        if (c + 1 < NC)
            load_stage(sb, (c + 1) & 1, c + 1, tid, A0, A1, B0, B1, K);
        asm volatile("cp.async.commit_group;\n" ::: "memory");
        asm volatile("cp.async.wait_group 1;\n" ::: "memory");
        __syncthreads();

        uint32_t st = sb + (uint32_t)(c & 1) * STAGE_B;
        uint32_t ah_b = st;
        uint32_t al_b = st + TILE_PB;
        uint32_t bh_b = st + 2*TILE_PB;
        uint32_t bl_b = st + 3*TILE_PB;

        #pragma unroll
        for (int ks = 0; ks < 2; ks++) {
            // cache ALL B fragments for this k-halfstep (16 regs)
            uint32_t bh2[2][4], bl2[2][4];
            #pragma unroll
            for (int nb = 0; nb < 2; nb++) {
                uint32_t boff = (uint32_t)((wn + nb*16 + b_row) * (RS*2) + b_cb + ks*32);
                ldsm_x4(bh2[nb], bh_b + boff);
                ldsm_x4(bl2[nb], bl_b + boff);
            }
            // each A fragment loaded exactly once
            #pragma unroll
            for (int mi = 0; mi < 4; mi++) {
                uint32_t ah[4], al[4];
                uint32_t aoff = (uint32_t)((wm + mi*16 + a_row) * (RS*2) + a_cb + ks*32);
                ldsm_x4(ah, ah_b + aoff);
                ldsm_x4(al, al_b + aoff);
                #pragma unroll
                for (int ni = 0; ni < 4; ni++) {
                    int nb = ni >> 1, hf = (ni & 1) * 2;
                    mma_bf16(d[mi][ni], ah, bh2[nb][hf], bh2[nb][hf+1]);
                    mma_bf16(d[mi][ni], ah, bl2[nb][hf], bl2[nb][hf+1]);
                    mma_bf16(d[mi][ni], al, bh2[nb][hf], bh2[nb][hf+1]);
                }
            }
        }
        __syncthreads();
    }

    const int q  = lane >> 2;
    const int tq = lane & 3;
    #pragma unroll
    for (int mi = 0; mi < 4; mi++) {
        int row0 = by*128 + wm + mi*16 + q;
        #pragma unroll
        for (int ni = 0; ni < 4; ni++) {
            int col = bx*128 + wn + ni*8 + tq*2;
            size_t off0 = (size_t)row0 * N + col;
            size_t off1 = off0 + (size_t)8 * N;
            float v0 = d[mi][ni][0], v1 = d[mi][ni][1];
            float v2 = d[mi][ni][2], v3 = d[mi][ni][3];
            if (EPI == 0) {
                *(float2*)(Cf + off0) = make_float2(v0, v1);
                *(float2*)(Cf + off1) = make_float2(v2, v3);
            } else if (EPI == 1) {
                float2 x0 = *(const float2*)(X + off0);
                float2 x1 = *(const float2*)(X + off1);
                *(float2*)(Cf + off0) = make_float2(v0 + x0.x, v1 + x0.y);
                *(float2*)(Cf + off1) = make_float2(v2 + x1.x, v3 + x1.y);
            } else if (EPI == 2) {
                // bx tile == one head (HD == 128). X = freqs table (S, HD/2, 2).
                int head = bx;
                if (head < NH + NKV) {
                    int cl = wn + ni*8 + tq*2;     // local col in head, even
                    int r0 = row0, r1 = row0 + 8;
                    int b0 = r0 >> 11;
                    int s0 = r0 & (SEQ-1), s1 = r1 & (SEQ-1);
                    float2 f0 = *(const float2*)(X + (size_t)s0*HD + cl);
                    float2 f1 = *(const float2*)(X + (size_t)s1*HD + cl);
                    float n00 = v0*f0.x - v1*f0.y, n01 = v1*f0.x + v0*f0.y;
                    float n10 = v2*f1.x - v3*f1.y, n11 = v3*f1.x + v2*f1.y;
                    if (head < NH) {
                        size_t o0 = ((size_t)(b0*NH + head)*SEQ + s0)*HD + cl;
                        size_t o1 = ((size_t)(b0*NH + head)*SEQ + s1)*HD + cl;
                        store_hl2(Qh2, Ql2, o0, n00, n01);
                        store_hl2(Qh2, Ql2, o1, n10, n11);
                    } else {
                        int kh = head - NH;
                        size_t o0 = ((size_t)(b0*NKV + kh)*SEQ + s0)*HD + cl;
                        size_t o1 = ((size_t)(b0*NKV + kh)*SEQ + s1)*HD + cl;
                        store_hl2(Kh2, Kl2, o0, n00, n01);
                        store_hl2(Kh2, Kl2, o1, n10, n11);
                    }
                } else {
                    *(float2*)(Cf + off0) = make_float2(v0, v1);
                    *(float2*)(Cf + off1) = make_float2(v2, v3);
                }
            } else {  // EPI 3
                float2 x0 = *(const float2*)(X + off0);
                float2 x1 = *(const float2*)(X + off1);
                store_hl2(Chi, Clo, off0, v0 * silu_f(x0.x), v1 * silu_f(x0.y));
                store_hl2(Chi, Clo, off1, v2 * silu_f(x1.x), v3 * silu_f(x1.y));
            }
        }
    }
}

// ================= HMMA flash attention (bf16x3, causal, GQA) ==================
#define AQ_RS   136
#define AV_RS   72
#define AQT_B   (128*AQ_RS*2)    // 34816
#define AKT_B   (64*AQ_RS*2)     // 17408
#define AVT_B   (128*AV_RS*2)    // 18432
#define ATTN_SMEM (2*AQT_B + 2*AKT_B + 2*AVT_B)   // 141312

__global__ __launch_bounds__(256, 1) void attn_hmma(
    const __nv_bfloat16* __restrict__ Qh, const __nv_bfloat16* __restrict__ Ql,
    const __nv_bfloat16* __restrict__ Kh, const __nv_bfloat16* __restrict__ Kl,
    const __nv_bfloat16* __restrict__ Vh, const __nv_bfloat16* __restrict__ Vl,
    __nv_bfloat16* __restrict__ Ohi, __nv_bfloat16* __restrict__ Olo)
{
    extern __shared__ char smem[];
    uint32_t sb = smem_u32(smem);
    uint32_t q_h = sb,            q_l = sb + AQT_B;
    uint32_t k_h = q_l + AQT_B,   k_l = k_h + AKT_B;
    uint32_t v_h = k_l + AKT_B,   v_l = v_h + AVT_B;

    const int tid = threadIdx.x, wid = tid >> 5, lane = tid & 31;
    const int bx = blockIdx.x, h = blockIdx.y, b = blockIdx.z;
    const int kvh = h >> 2;
    const int q0 = bx * 128;

    const __nv_bfloat16* gQh = Qh + ((size_t)(b*NH + h) * SEQ + q0) * HD;
    const __nv_bfloat16* gQl = Ql + ((size_t)(b*NH + h) * SEQ + q0) * HD;
    const __nv_bfloat16* gKh = Kh + (size_t)(b*NKV + kvh) * SEQ * HD;
    const __nv_bfloat16* gKl = Kl + (size_t)(b*NKV + kvh) * SEQ * HD;
    const __nv_bfloat16* gVh = Vh + (size_t)(b*NKV + kvh) * HD * SEQ;
    const __nv_bfloat16* gVl = Vl + (size_t)(b*NKV + kvh) * HD * SEQ;

    #pragma unroll
    for (int i = 0; i < 8; i++) {
        int ch = i * 256 + tid;
        int r = ch >> 4, cc = ch & 15;
        uint32_t so = (uint32_t)(r * (AQ_RS*2) + cc * 16);
        cpa16(q_h + so, gQh + (size_t)r * HD + cc * 8);
        cpa16(q_l + so, gQl + (size_t)r * HD + cc * 8);
    }
    asm volatile("cp.async.commit_group;\n" ::: "memory");

    float O[16][4];
    #pragma unroll
    for (int i = 0; i < 16; i++)
        #pragma unroll
        for (int j = 0; j < 4; j++) O[i][j] = 0.0f;
    float m0 = -1e30f, m1 = -1e30f, l0 = 0.0f, l1 = 0.0f;

    const int a_row = lane & 15;
    const int a_cb  = (lane >> 4) * 16;
    const int b_row = (lane & 7) | ((lane >> 1) & 8);
    const int b_cb  = ((lane >> 3) & 1) * 16;
    const int r0g = q0 + wid*16 + (lane >> 2);
    const int r1g = r0g + 8;
    const float scale = rsqrtf((float)EMBED);

    const int ktiles = 2*bx + 2;
    for (int kt = 0; kt < ktiles; kt++) {
        int k0 = kt * 64;
        __syncthreads();
        #pragma unroll
        for (int i = 0; i < 4; i++) {
            int ch = i * 256 + tid;
            int r = ch >> 4, cc = ch & 15;
            uint32_t so = (uint32_t)(r * (AQ_RS*2) + cc * 16);
            cpa16(k_h + so, gKh + (size_t)(k0 + r) * HD + cc * 8);
            cpa16(k_l + so, gKl + (size_t)(k0 + r) * HD + cc * 8);
        }
        #pragma unroll
        for (int i = 0; i < 4; i++) {
            int ch = i * 256 + tid;
            int r = ch >> 3, cc = ch & 7;
            uint32_t so = (uint32_t)(r * (AV_RS*2) + cc * 16);
            cpa16(v_h + so, gVh + (size_t)r * SEQ + k0 + cc * 8);
            cpa16(v_l + so, gVl + (size_t)r * SEQ + k0 + cc * 8);
        }
        asm volatile("cp.async.commit_group;\n" ::: "memory");
        asm volatile("cp.async.wait_group 0;\n" ::: "memory");
        __syncthreads();

        float S[8][4];
        #pragma unroll
        for (int i = 0; i < 8; i++)
            #pragma unroll
            for (int j = 0; j < 4; j++) S[i][j] = 0.0f;

        #pragma unroll
        for (int kk = 0; kk < 8; kk++) {
            uint32_t ah[4], al[4];
            uint32_t aoff = (uint32_t)((wid*16 + a_row) * (AQ_RS*2) + a_cb + kk*32);
            ldsm_x4(ah, q_h + aoff);
            ldsm_x4(al, q_l + aoff);
            #pragma unroll
            for (int np = 0; np < 4; np++) {
                uint32_t bh[4], bl[4];
                uint32_t boff = (uint32_t)((np*16 + b_row) * (AQ_RS*2) + b_cb + kk*32);
                ldsm_x4(bh, k_h + boff);
                ldsm_x4(bl, k_l + boff);
                mma_bf16(S[2*np],   ah, bh[0], bh[1]);
                mma_bf16(S[2*np],   ah, bl[0], bl[1]);
                mma_bf16(S[2*np],   al, bh[0], bh[1]);
                mma_bf16(S[2*np+1], ah, bh[2], bh[3]);
                mma_bf16(S[2*np+1], ah, bl[2], bl[3]);
                mma_bf16(S[2*np+1], al, bh[2], bh[3]);
            }
        }

        #pragma unroll
        for (int ni = 0; ni < 8; ni++) {
            int c0 = k0 + ni*8 + 2*(lane & 3);
            S[ni][0] = (c0     > r0g) ? -1e30f : S[ni][0] * scale;
            S[ni][1] = (c0 + 1 > r0g) ? -1e30f : S[ni][1] * scale;
            S[ni][2] = (c0     > r1g) ? -1e30f : S[ni][2] * scale;
            S[ni][3] = (c0 + 1 > r1g) ? -1e30f : S[ni][3] * scale;
        }

        float mx0 = -1e30f, mx1 = -1e30f;
        #pragma unroll
        for (int ni = 0; ni < 8; ni++) {
            mx0 = fmaxf(mx0, fmaxf(S[ni][0], S[ni][1]));
            mx1 = fmaxf(mx1, fmaxf(S[ni][2], S[ni][3]));
        }
        mx0 = fmaxf(mx0, __shfl_xor_sync(0xffffffffu, mx0, 1));
        mx0 = fmaxf(mx0, __shfl_xor_sync(0xffffffffu, mx0, 2));
        mx1 = fmaxf(mx1, __shfl_xor_sync(0xffffffffu, mx1, 1));
        mx1 = fmaxf(mx1, __shfl_xor_sync(0xffffffffu, mx1, 2));
        float mn0 = fmaxf(m0, mx0), mn1 = fmaxf(m1, mx1);
        float corr0 = __expf(m0 - mn0), corr1 = __expf(m1 - mn1);
        m0 = mn0; m1 = mn1;

        uint32_t PH[8][2], PL[8][2];
        float ls0 = 0.0f, ls1 = 0.0f;
        #pragma unroll
        for (int ni = 0; ni < 8; ni++) {
            float p0 = __expf(S[ni][0] - mn0);
            float p1 = __expf(S[ni][1] - mn0);
            float p2 = __expf(S[ni][2] - mn1);
            float p3 = __expf(S[ni][3] - mn1);
            ls0 += p0 + p1; ls1 += p2 + p3;
            uint32_t h01 = packbf(p0, p1);
            uint32_t h23 = packbf(p2, p3);
            PH[ni][0] = h01; PH[ni][1] = h23;
            float h0f = __uint_as_float(h01 << 16);
            float h1f = __uint_as_float(h01 & 0xffff0000u);
            float h2f = __uint_as_float(h23 << 16);
            float h3f = __uint_as_float(h23 & 0xffff0000u);
            PL[ni][0] = packbf(p0 - h0f, p1 - h1f);
            PL[ni][1] = packbf(p2 - h2f, p3 - h3f);
        }
        ls0 += __shfl_xor_sync(0xffffffffu, ls0, 1);
        ls0 += __shfl_xor_sync(0xffffffffu, ls0, 2);
        ls1 += __shfl_xor_sync(0xffffffffu, ls1, 1);
        ls1 += __shfl_xor_sync(0xffffffffu, ls1, 2);
        l0 = l0 * corr0 + ls0;
        l1 = l1 * corr1 + ls1;

        #pragma unroll
        for (int nb = 0; nb < 16; nb++) {
            O[nb][0] *= corr0; O[nb][1] *= corr0;
            O[nb][2] *= corr1; O[nb][3] *= corr1;
        }

        #pragma unroll
        for (int kc = 0; kc < 4; kc++) {
            uint32_t ah2[4] = {PH[2*kc][0], PH[2*kc][1], PH[2*kc+1][0], PH[2*kc+1][1]};
            uint32_t al2[4] = {PL[2*kc][0], PL[2*kc][1], PL[2*kc+1][0], PL[2*kc+1][1]};
            #pragma unroll
            for (int dp = 0; dp < 8; dp++) {
                uint32_t bh[4], bl[4];
                uint32_t boff = (uint32_t)((dp*16 + b_row) * (AV_RS*2) + b_cb + kc*32);
                ldsm_x4(bh, v_h + boff);
                ldsm_x4(bl, v_l + boff);
                mma_bf16(O[2*dp],   ah2, bh[0], bh[1]);
                mma_bf16(O[2*dp],   al2, bh[0], bh[1]);
                mma_bf16(O[2*dp],   ah2, bl[0], bl[1]);
                mma_bf16(O[2*dp+1], ah2, bh[2], bh[3]);
                mma_bf16(O[2*dp+1], al2, bh[2], bh[3]);
                mma_bf16(O[2*dp+1], ah2, bl[2], bl[3]);
            }
        }
    }

    float inv0 = 1.0f / l0, inv1 = 1.0f / l1;
    #pragma unroll
    for (int nb = 0; nb < 16; nb++) {
        int col = h*HD + nb*8 + 2*(lane & 3);
        size_t o0 = ((size_t)(b*SEQ) + r0g) * EMBED + col;
        size_t o1 = ((size_t)(b*SEQ) + r1g) * EMBED + col;
        store_hl2(Ohi, Olo, o0, O[nb][0]*inv0, O[nb][1]*inv0);
        store_hl2(Ohi, Olo, o1, O[nb][2]*inv1, O[nb][3]*inv1);
    }
}

// ================= launcher ====================================================
extern "C" void kernel_launch(void* const* d_in, const int* in_sizes, int n_in,
                              void* d_out, int out_size)
{
    const float* x      = (const float*)d_in[0];
    const float* freqs  = (const float*)d_in[2];
    const float* w_qkv  = (const float*)d_in[4];
    const float* w_fc   = (const float*)d_in[5];
    const float* w1     = (const float*)d_in[6];
    const float* w2     = (const float*)d_in[7];
    const float* w3     = (const float*)d_in[8];
    const float* attn_w = (const float*)d_in[9];
    const float* ff_w   = (const float*)d_in[10];
    float* out = (float*)d_out;

    float *qkv, *h2, *ff1;
    __nv_bfloat16 *nhi, *nlo, *ahi, *alo, *fhi, *flo;
    __nv_bfloat16 *qh, *ql, *kh, *kl, *vh, *vl;
    __nv_bfloat16 *wqh, *wql, *wfh, *wfl, *w1h, *w1l, *w2h, *w2l, *w3h, *w3l;
    cudaGetSymbolAddress((void**)&qkv,  g_qkv);
    cudaGetSymbolAddress((void**)&h2,   g_h2);
    cudaGetSymbolAddress((void**)&ff1,  g_ff1);
    cudaGetSymbolAddress((void**)&nhi,  g_nhi);  cudaGetSymbolAddress((void**)&nlo, g_nlo);
    cudaGetSymbolAddress((void**)&ahi,  g_ahi);  cudaGetSymbolAddress((void**)&alo, g_alo);
    cudaGetSymbolAddress((void**)&fhi,  g_fhi);  cudaGetSymbolAddress((void**)&flo, g_flo);
    cudaGetSymbolAddress((void**)&qh,   g_qh);   cudaGetSymbolAddress((void**)&ql,  g_ql);
    cudaGetSymbolAddress((void**)&kh,   g_kh);   cudaGetSymbolAddress((void**)&kl,  g_kl);
    cudaGetSymbolAddress((void**)&vh,   g_vh);   cudaGetSymbolAddress((void**)&vl,  g_vl);
    cudaGetSymbolAddress((void**)&wqh,  g_wqkv_h); cudaGetSymbolAddress((void**)&wql, g_wqkv_l);
    cudaGetSymbolAddress((void**)&wfh,  g_wfc_h);  cudaGetSymbolAddress((void**)&wfl, g_wfc_l);
    cudaGetSymbolAddress((void**)&w1h,  g_w1_h);   cudaGetSymbolAddress((void**)&w1l, g_w1_l);
    cudaGetSymbolAddress((void**)&w2h,  g_w2_h);   cudaGetSymbolAddress((void**)&w2l, g_w2_l);
    cudaGetSymbolAddress((void**)&w3h,  g_w3_h);   cudaGetSymbolAddress((void**)&w3l, g_w3_l);

    cudaFuncSetAttribute((const void*)attn_hmma,
                         cudaFuncAttributeMaxDynamicSharedMemorySize, ATTN_SMEM);
    cudaFuncSetAttribute((const void*)hmma_gemm<0>,
                         cudaFuncAttributeMaxDynamicSharedMemorySize, GEMM_SMEM);
    cudaFuncSetAttribute((const void*)hmma_gemm<1>,
                         cudaFuncAttributeMaxDynamicSharedMemorySize, GEMM_SMEM);
    cudaFuncSetAttribute((const void*)hmma_gemm<2>,
                         cudaFuncAttributeMaxDynamicSharedMemorySize, GEMM_SMEM);
    cudaFuncSetAttribute((const void*)hmma_gemm<3>,
                         cudaFuncAttributeMaxDynamicSharedMemorySize, GEMM_SMEM);

    // weight hi/lo conversion
    cvt_hl<<<(QKV_N*EMBED/4 + 255)/256, 256>>>(w_qkv, wqh, wql, QKV_N*EMBED/4);
    cvt_hl<<<(EMBED*EMBED/4 + 255)/256, 256>>>(w_fc,  wfh, wfl, EMBED*EMBED/4);
    cvt_hl<<<(FF*EMBED/4 + 255)/256, 256>>>(w1, w1h, w1l, FF*EMBED/4);
    cvt_hl<<<(FF*EMBED/4 + 255)/256, 256>>>(w2, w2h, w2l, FF*EMBED/4);
    cvt_hl<<<(EMBED*FF/4 + 255)/256, 256>>>(w3, w3h, w3l, EMBED*FF/4);

    // 1) g = rmsnorm(x) -> hi/lo
    rmsnorm_hl<<<ROWS, 256>>>(x, attn_w, nhi, nlo);
    // 2) qkv GEMM with fused RoPE + hi/lo split (Q,K head-major) ; V -> fp32 qkv
    hmma_gemm<2><<<dim3(QKV_N/128, ROWS/128), 256, GEMM_SMEM>>>(
        nhi, nlo, wqh, wql, qkv, freqs, nullptr, nullptr,
        qh, ql, kh, kl, ROWS, QKV_N, EMBED);
    // 3) V transpose + split
    v_split_t<<<dim3(SEQ/32, HD/32, BATCH*NKV), 256>>>(qkv, vh, vl);
    // 4) attention (HMMA bf16x3) -> ahi/alo
    attn_hmma<<<dim3(SEQ/128, NH, BATCH), 256, ATTN_SMEM>>>(
        qh, ql, kh, kl, vh, vl, ahi, alo);
    // 5) h2 = x + attn @ w_fc^T
    hmma_gemm<1><<<dim3(EMBED/128, ROWS/128), 256, GEMM_SMEM>>>(
        ahi, alo, wfh, wfl, h2, x, nullptr, nullptr,
        nullptr, nullptr, nullptr, nullptr, ROWS, EMBED, EMBED);
    // 6) g2 = rmsnorm(h2) -> hi/lo
    rmsnorm_hl<<<ROWS, 256>>>(h2, ff_w, nhi, nlo);
    // 7) ff1 = g2 @ w1^T (fp32)
    hmma_gemm<0><<<dim3(FF/128, ROWS/128), 256, GEMM_SMEM>>>(
        nhi, nlo, w1h, w1l, ff1, nullptr, nullptr, nullptr,
        nullptr, nullptr, nullptr, nullptr, ROWS, FF, EMBED);
    // 8) ff = silu(ff1) * (g2 @ w2^T) -> hi/lo
    hmma_gemm<3><<<dim3(FF/128, ROWS/128), 256, GEMM_SMEM>>>(
        nhi, nlo, w2h, w2l, nullptr, ff1, fhi, flo,
        nullptr, nullptr, nullptr, nullptr, ROWS, FF, EMBED);
    // 9) out = h2 + ff @ w3^T
    hmma_gemm<1><<<dim3(EMBED/128, ROWS/128), 256, GEMM_SMEM>>>(
        fhi, flo, w3h, w3l, out, h2, nullptr, nullptr,
        nullptr, nullptr, nullptr, nullptr, ROWS, EMBED, FF);
}

// round 9
// speedup vs baseline: 1.4289x; 1.4289x over previous
#include <cuda_runtime.h>
#include <cuda_fp16.h>
#include <math.h>
#include <cstdint>

// Problem constants
#define BATCH 2
#define SEQ   2048
#define EMBED 2048
#define NH    16
#define NKV   4
#define HD    128
#define FF    5632
#define ROWS  (BATCH*SEQ)          // 4096
#define QKV_N ((NH + 2*NKV)*HD)    // 3072

// ================= scratch (static device globals) =============================
__device__ float g_qkv [ROWS*QKV_N];   // only V columns written (fused qkv epilogue)
__device__ float g_h2  [ROWS*EMBED];
__device__ float g_ff1 [ROWS*FF];
__device__ __half g_n [ROWS*EMBED];          // rmsnorm out (single fp16)
__device__ __half g_a [ROWS*EMBED];          // attention out
__device__ __half g_f [ROWS*FF];             // silu*mul out
__device__ __half g_q [ROWS*NH*HD];          // head-major Q (roped)
__device__ __half g_k [ROWS*NKV*HD];         // head-major K (roped)
__device__ __half g_v [ROWS*NKV*HD];         // V transposed [b,kh,d,s]
__device__ __half g_wqkv_h[QKV_N*EMBED], g_wqkv_l[QKV_N*EMBED];
__device__ __half g_wfc_h[EMBED*EMBED],  g_wfc_l[EMBED*EMBED];
__device__ __half g_w1_h[FF*EMBED],      g_w1_l[FF*EMBED];
__device__ __half g_w2_h[FF*EMBED],      g_w2_l[FF*EMBED];
__device__ __half g_w3_h[EMBED*FF],      g_w3_l[EMBED*FF];

// ================= helpers =====================================================
__device__ __forceinline__ float silu_f(float z) { return z / (1.0f + __expf(-z)); }

__device__ __forceinline__ uint32_t smem_u32(const void* p) {
    uint32_t a;
    asm("{ .reg .u64 t; cvta.to.shared.u64 t, %1; cvt.u32.u64 %0, t; }" : "=r"(a) : "l"(p));
    return a;
}
__device__ __forceinline__ void cpa16(uint32_t so, const void* ga) {
    asm volatile("cp.async.cg.shared.global [%0], [%1], 16;\n" :: "r"(so), "l"(ga));
}
__device__ __forceinline__ void ldsm_x4(uint32_t (&r)[4], uint32_t addr) {
    asm volatile("ldmatrix.sync.aligned.m8n8.x4.shared.b16 {%0,%1,%2,%3}, [%4];"
                 : "=r"(r[0]), "=r"(r[1]), "=r"(r[2]), "=r"(r[3]) : "r"(addr));
}
__device__ __forceinline__ void mma_f16(float (&d)[4], const uint32_t (&a)[4],
                                        uint32_t b0, uint32_t b1) {
    asm volatile(
        "mma.sync.aligned.m16n8k16.row.col.f32.f16.f16.f32 "
        "{%0,%1,%2,%3}, {%4,%5,%6,%7}, {%8,%9}, {%0,%1,%2,%3};"
        : "+f"(d[0]), "+f"(d[1]), "+f"(d[2]), "+f"(d[3])
        : "r"(a[0]), "r"(a[1]), "r"(a[2]), "r"(a[3]), "r"(b0), "r"(b1));
}
// pack two fp32 -> f16x2 (first arg -> low half)
__device__ __forceinline__ uint32_t packh(float lo, float hi) {
    uint32_t d;
    asm("cvt.rn.f16x2.f32 %0, %1, %2;" : "=r"(d) : "f"(hi), "f"(lo));
    return d;
}
__device__ __forceinline__ void store_h2g(__half* __restrict__ p, size_t idx,
                                          float a, float b) {
    __half2 v; v.x = __float2half_rn(a); v.y = __float2half_rn(b);
    *(__half2*)(p + idx) = v;
}
__device__ __forceinline__ void store_h4g(__half* __restrict__ p, size_t idx,
                                          float a, float b, float c, float d) {
    __half2 v0, v1;
    v0.x = __float2half_rn(a); v0.y = __float2half_rn(b);
    v1.x = __float2half_rn(c); v1.y = __float2half_rn(d);
    *(__half2*)(p + idx)     = v0;
    *(__half2*)(p + idx + 2) = v1;
}

// fp32 -> (hi, lo) fp16 split (weights prepass)
__global__ __launch_bounds__(256) void cvt_hl_f16(
    const float* __restrict__ src, __half* __restrict__ hi,
    __half* __restrict__ lo, int n4)
{
    int i = blockIdx.x * 256 + threadIdx.x;
    if (i >= n4) return;
    float4 v = ((const float4*)src)[i];
    size_t idx = (size_t)i * 4;
    __half h0 = __float2half_rn(v.x), h1 = __float2half_rn(v.y);
    __half h2 = __float2half_rn(v.z), h3 = __float2half_rn(v.w);
    __half l0 = __float2half_rn(v.x - __half2float(h0));
    __half l1 = __float2half_rn(v.y - __half2float(h1));
    __half l2 = __float2half_rn(v.z - __half2float(h2));
    __half l3 = __float2half_rn(v.w - __half2float(h3));
    __half2 p;
    p.x = h0; p.y = h1; *(__half2*)(hi + idx)     = p;
    p.x = h2; p.y = h3; *(__half2*)(hi + idx + 2) = p;
    p.x = l0; p.y = l1; *(__half2*)(lo + idx)     = p;
    p.x = l2; p.y = l3; *(__half2*)(lo + idx + 2) = p;
}

// rmsnorm with single fp16 output
__global__ __launch_bounds__(256) void rmsnorm_h(
    const float* __restrict__ x, const float* __restrict__ w,
    __half* __restrict__ o)
{
    int row = blockIdx.x;
    const float4* xr = (const float4*)(x + (size_t)row * EMBED);
    int t = threadIdx.x;
    float4 v0 = xr[t];
    float4 v1 = xr[t + 256];
    float ss = v0.x*v0.x + v0.y*v0.y + v0.z*v0.z + v0.w*v0.w
             + v1.x*v1.x + v1.y*v1.y + v1.z*v1.z + v1.w*v1.w;
    #pragma unroll
    for (int m = 16; m; m >>= 1) ss += __shfl_xor_sync(0xffffffffu, ss, m);
    __shared__ float red[8];
    if ((t & 31) == 0) red[t >> 5] = ss;
    __syncthreads();
    float tot = red[0]+red[1]+red[2]+red[3]+red[4]+red[5]+red[6]+red[7];
    float r = rsqrtf(tot * (1.0f/EMBED) + 1e-5f);
    const float4* wr = (const float4*)w;
    float4 w0 = wr[t], w1 = wr[t + 256];
    size_t base = (size_t)row * EMBED;
    store_h4g(o, base + t*4,        v0.x*r*w0.x, v0.y*r*w0.y, v0.z*r*w0.z, v0.w*r*w0.w);
    store_h4g(o, base + 1024 + t*4, v1.x*r*w1.x, v1.y*r*w1.y, v1.z*r*w1.z, v1.w*r*w1.w);
}

// ---------------- V: transpose to [b,kh,d,s] + fp16 ---------------------------
__global__ __launch_bounds__(256) void v_split_t(
    const float* __restrict__ qkv, __half* __restrict__ vh)
{
    __shared__ float tile[32][33];
    int s0 = blockIdx.x * 32, d0 = blockIdx.y * 32;
    int b  = blockIdx.z >> 2, kh = blockIdx.z & 3;
    int tx = threadIdx.x & 31, ty = threadIdx.x >> 5;   // 32 x 8
    #pragma unroll
    for (int i = 0; i < 4; i++) {
        int s = s0 + ty + i*8;
        tile[ty + i*8][tx] = qkv[(size_t)(b*SEQ + s) * QKV_N + (NH+NKV)*HD + kh*HD + d0 + tx];
    }
    __syncthreads();
    #pragma unroll
    for (int i = 0; i < 4; i++) {
        int d = d0 + ty + i*8;
        float v = tile[tx][ty + i*8];
        size_t o = ((size_t)(b*NKV + kh) * HD + d) * SEQ + s0 + tx;
        vh[o] = __float2half_rn(v);
    }
}

// ================= HMMA fp16x2 GEMM ============================================
// C[M,N] = A[M,K] @ W[N,K]^T ; A single fp16, W = (Wh, Wl) fp16 pair.
// EPI 0: Cf = acc
// EPI 1: Cf = acc + X
// EPI 2: qkv fused: Q/K heads -> RoPE fp16 head-major (X = freqs); V -> fp32 Cf
// EPI 3: Ch = fp16(acc * silu(X))
#define BKC      32
#define RS       40
#define TILE_PB  (128*RS*2)            // 10240
#define STAGE_B  (3*TILE_PB)           // A, Wh, Wl
#define NSTAGE   2
#define GEMM_SMEM (NSTAGE*STAGE_B)     // 61440

__device__ __forceinline__ void load_stage(
    uint32_t sb, int stage, int chunk, int tid,
    const __half* __restrict__ A, const __half* __restrict__ B0,
    const __half* __restrict__ B1, int K)
{
    const __half* mats[3] = {A, B0, B1};
    uint32_t stage_base = sb + (uint32_t)stage * STAGE_B;
    #pragma unroll
    for (int m = 0; m < 3; m++) {
        const __half* gp = mats[m] + chunk * BKC;
        uint32_t tb = stage_base + m * TILE_PB;
        #pragma unroll
        for (int it = 0; it < 2; it++) {
            int ch = it * 256 + tid;
            int r  = ch >> 2;
            int cc = ch & 3;
            uint32_t so = tb + (uint32_t)(r * (RS*2) + cc * 16);
            cpa16(so, gp + (size_t)r * K + cc * 8);
        }
    }
}

template<int EPI>
__global__ __launch_bounds__(256, 2) void hmma_gemm(
    const __half* __restrict__ A, const __half* __restrict__ Bh,
    const __half* __restrict__ Bl,
    float* __restrict__ Cf, const float* __restrict__ X,
    __half* __restrict__ Ch,
    __half* __restrict__ Qo, __half* __restrict__ Ko,
    int M, int N, int K)
{
    extern __shared__ char smem[];
    uint32_t sb = smem_u32(smem);
    const int tid  = threadIdx.x;
    const int wid  = tid >> 5;
    const int lane = tid & 31;
    const int bx = blockIdx.x, by = blockIdx.y;
    const int wm = (wid >> 2) * 64;
    const int wn = (wid & 3) * 32;

    const __half* A0 = A  + (size_t)by * 128 * K;
    const __half* B0 = Bh + (size_t)bx * 128 * K;
    const __half* B1 = Bl + (size_t)bx * 128 * K;

    float d[4][4][4];
    #pragma unroll
    for (int i = 0; i < 4; i++)
        #pragma unroll
        for (int j = 0; j < 4; j++)
            #pragma unroll
            for (int r = 0; r < 4; r++) d[i][j][r] = 0.0f;

    const int a_row = lane & 15;
    const int a_cb  = (lane >> 4) * 16;
    const int b_row = (lane & 7) | ((lane >> 1) & 8);
    const int b_cb  = ((lane >> 3) & 1) * 16;

    const int NC = K / BKC;

    load_stage(sb, 0, 0, tid, A0, B0, B1, K);
    asm volatile("cp.async.commit_group;\n" ::: "memory");

    for (int c = 0; c < NC; c++) {
        if (c + 1 < NC)
            load_stage(sb, (c + 1) & 1, c + 1, tid, A0, B0, B1, K);
        asm volatile("cp.async.commit_group;\n" ::: "memory");
        asm volatile("cp.async.wait_group 1;\n" ::: "memory");
        __syncthreads();

        uint32_t st = sb + (uint32_t)(c & 1) * STAGE_B;
        uint32_t a_b  = st;
        uint32_t bh_b = st + TILE_PB;
        uint32_t bl_b = st + 2*TILE_PB;

        #pragma unroll
        for (int ks = 0; ks < 2; ks++) {
            uint32_t bh2[2][4], bl2[2][4];
            #pragma unroll
            for (int nb = 0; nb < 2; nb++) {
                uint32_t boff = (uint32_t)((wn + nb*16 + b_row) * (RS*2) + b_cb + ks*32);
                ldsm_x4(bh2[nb], bh_b + boff);
                ldsm_x4(bl2[nb], bl_b + boff);
            }
            #pragma unroll
            for (int mi = 0; mi < 4; mi++) {
                uint32_t av[4];
                uint32_t aoff = (uint32_t)((wm + mi*16 + a_row) * (RS*2) + a_cb + ks*32);
                ldsm_x4(av, a_b + aoff);
                #pragma unroll
                for (int ni = 0; ni < 4; ni++) {
                    int nb = ni >> 1, hf = (ni & 1) * 2;
                    mma_f16(d[mi][ni], av, bh2[nb][hf], bh2[nb][hf+1]);
                    mma_f16(d[mi][ni], av, bl2[nb][hf], bl2[nb][hf+1]);
                }
            }
        }
        __syncthreads();
    }

    const int q  = lane >> 2;
    const int tq = lane & 3;
    #pragma unroll
    for (int mi = 0; mi < 4; mi++) {
        int row0 = by*128 + wm + mi*16 + q;
        #pragma unroll
        for (int ni = 0; ni < 4; ni++) {
            int col = bx*128 + wn + ni*8 + tq*2;
            size_t off0 = (size_t)row0 * N + col;
            size_t off1 = off0 + (size_t)8 * N;
            float v0 = d[mi][ni][0], v1 = d[mi][ni][1];
            float v2 = d[mi][ni][2], v3 = d[mi][ni][3];
            if (EPI == 0) {
                *(float2*)(Cf + off0) = make_float2(v0, v1);
                *(float2*)(Cf + off1) = make_float2(v2, v3);
            } else if (EPI == 1) {
                float2 x0 = *(const float2*)(X + off0);
                float2 x1 = *(const float2*)(X + off1);
                *(float2*)(Cf + off0) = make_float2(v0 + x0.x, v1 + x0.y);
                *(float2*)(Cf + off1) = make_float2(v2 + x1.x, v3 + x1.y);
            } else if (EPI == 2) {
                // bx tile == one head (HD == 128). X = freqs table (S, HD/2, 2).
                int head = bx;
                if (head < NH + NKV) {
                    int cl = wn + ni*8 + tq*2;
                    int r0 = row0, r1 = row0 + 8;
                    int b0 = r0 >> 11;
                    int s0 = r0 & (SEQ-1), s1 = r1 & (SEQ-1);
                    float2 f0 = *(const float2*)(X + (size_t)s0*HD + cl);
                    float2 f1 = *(const float2*)(X + (size_t)s1*HD + cl);
                    float n00 = v0*f0.x - v1*f0.y, n01 = v1*f0.x + v0*f0.y;
                    float n10 = v2*f1.x - v3*f1.y, n11 = v3*f1.x + v2*f1.y;
                    if (head < NH) {
                        size_t o0 = ((size_t)(b0*NH + head)*SEQ + s0)*HD + cl;
                        size_t o1 = ((size_t)(b0*NH + head)*SEQ + s1)*HD + cl;
                        store_h2g(Qo, o0, n00, n01);
                        store_h2g(Qo, o1, n10, n11);
                    } else {
                        int kh = head - NH;
                        size_t o0 = ((size_t)(b0*NKV + kh)*SEQ + s0)*HD + cl;
                        size_t o1 = ((size_t)(b0*NKV + kh)*SEQ + s1)*HD + cl;
                        store_h2g(Ko, o0, n00, n01);
                        store_h2g(Ko, o1, n10, n11);
                    }
                } else {
                    *(float2*)(Cf + off0) = make_float2(v0, v1);
                    *(float2*)(Cf + off1) = make_float2(v2, v3);
                }
            } else {  // EPI 3
                float2 x0 = *(const float2*)(X + off0);
                float2 x1 = *(const float2*)(X + off1);
                store_h2g(Ch, off0, v0 * silu_f(x0.x), v1 * silu_f(x0.y));
                store_h2g(Ch, off1, v2 * silu_f(x1.x), v3 * silu_f(x1.y));
            }
        }
    }
}

// ================= HMMA flash attention (fp16, causal, GQA) ====================
// Q,K,V single fp16; scores = 1 product; P split hi/lo x V = 2 products.
#define AQ_RS   136
#define AV_RS   72
#define AQT_B   (128*AQ_RS*2)    // 34816
#define AKT_B   (64*AQ_RS*2)     // 17408
#define AVT_B   (128*AV_RS*2)    // 18432
#define ATTN_SMEM (AQT_B + AKT_B + AVT_B)   // 70656

__global__ __launch_bounds__(256, 2) void attn_hmma(
    const __half* __restrict__ Q, const __half* __restrict__ Kg,
    const __half* __restrict__ Vg, __half* __restrict__ Oh)
{
    extern __shared__ char smem[];
    uint32_t sb = smem_u32(smem);
    uint32_t q_s = sb;
    uint32_t k_s = sb + AQT_B;
    uint32_t v_s = k_s + AKT_B;

    const int tid = threadIdx.x, wid = tid >> 5, lane = tid & 31;
    const int bx = blockIdx.x, h = blockIdx.y, b = blockIdx.z;
    const int kvh = h >> 2;
    const int q0 = bx * 128;

    const __half* gQ = Q  + ((size_t)(b*NH + h) * SEQ + q0) * HD;
    const __half* gK = Kg + (size_t)(b*NKV + kvh) * SEQ * HD;
    const __half* gV = Vg + (size_t)(b*NKV + kvh) * HD * SEQ;

    #pragma unroll
    for (int i = 0; i < 8; i++) {
        int ch = i * 256 + tid;
        int r = ch >> 4, cc = ch & 15;
        uint32_t so = (uint32_t)(r * (AQ_RS*2) + cc * 16);
        cpa16(q_s + so, gQ + (size_t)r * HD + cc * 8);
    }
    asm volatile("cp.async.commit_group;\n" ::: "memory");

    float O[16][4];
    #pragma unroll
    for (int i = 0; i < 16; i++)
        #pragma unroll
        for (int j = 0; j < 4; j++) O[i][j] = 0.0f;
    float m0 = -1e30f, m1 = -1e30f, l0 = 0.0f, l1 = 0.0f;

    const int a_row = lane & 15;
    const int a_cb  = (lane >> 4) * 16;
    const int b_row = (lane & 7) | ((lane >> 1) & 8);
    const int b_cb  = ((lane >> 3) & 1) * 16;
    const int r0g = q0 + wid*16 + (lane >> 2);
    const int r1g = r0g + 8;
    const float scale = rsqrtf((float)EMBED);

    const int ktiles = 2*bx + 2;
    for (int kt = 0; kt < ktiles; kt++) {
        int k0 = kt * 64;
        __syncthreads();
        #pragma unroll
        for (int i = 0; i < 4; i++) {
            int ch = i * 256 + tid;
            int r = ch >> 4, cc = ch & 15;
            uint32_t so = (uint32_t)(r * (AQ_RS*2) + cc * 16);
            cpa16(k_s + so, gK + (size_t)(k0 + r) * HD + cc * 8);
        }
        #pragma unroll
        for (int i = 0; i < 4; i++) {
            int ch = i * 256 + tid;
            int r = ch >> 3, cc = ch & 7;
            uint32_t so = (uint32_t)(r * (AV_RS*2) + cc * 16);
            cpa16(v_s + so, gV + (size_t)r * SEQ + k0 + cc * 8);
        }
        asm volatile("cp.async.commit_group;\n" ::: "memory");
        asm volatile("cp.async.wait_group 0;\n" ::: "memory");
        __syncthreads();

        float S[8][4];
        #pragma unroll
        for (int i = 0; i < 8; i++)
            #pragma unroll
            for (int j = 0; j < 4; j++) S[i][j] = 0.0f;

        #pragma unroll
        for (int kk = 0; kk < 8; kk++) {
            uint32_t av[4];
            uint32_t aoff = (uint32_t)((wid*16 + a_row) * (AQ_RS*2) + a_cb + kk*32);
            ldsm_x4(av, q_s + aoff);
            #pragma unroll
            for (int np = 0; np < 4; np++) {
                uint32_t bv[4];
                uint32_t boff = (uint32_t)((np*16 + b_row) * (AQ_RS*2) + b_cb + kk*32);
                ldsm_x4(bv, k_s + boff);
                mma_f16(S[2*np],   av, bv[0], bv[1]);
                mma_f16(S[2*np+1], av, bv[2], bv[3]);
            }
        }

        #pragma unroll
        for (int ni = 0; ni < 8; ni++) {
            int c0 = k0 + ni*8 + 2*(lane & 3);
            S[ni][0] = (c0     > r0g) ? -1e30f : S[ni][0] * scale;
            S[ni][1] = (c0 + 1 > r0g) ? -1e30f : S[ni][1] * scale;
            S[ni][2] = (c0     > r1g) ? -1e30f : S[ni][2] * scale;
            S[ni][3] = (c0 + 1 > r1g) ? -1e30f : S[ni][3] * scale;
        }

        float mx0 = -1e30f, mx1 = -1e30f;
        #pragma unroll
        for (int ni = 0; ni < 8; ni++) {
            mx0 = fmaxf(mx0, fmaxf(S[ni][0], S[ni][1]));
            mx1 = fmaxf(mx1, fmaxf(S[ni][2], S[ni][3]));
        }
        mx0 = fmaxf(mx0, __shfl_xor_sync(0xffffffffu, mx0, 1));
        mx0 = fmaxf(mx0, __shfl_xor_sync(0xffffffffu, mx0, 2));
        mx1 = fmaxf(mx1, __shfl_xor_sync(0xffffffffu, mx1, 1));
        mx1 = fmaxf(mx1, __shfl_xor_sync(0xffffffffu, mx1, 2));
        float mn0 = fmaxf(m0, mx0), mn1 = fmaxf(m1, mx1);
        float corr0 = __expf(m0 - mn0), corr1 = __expf(m1 - mn1);
        m0 = mn0; m1 = mn1;

        uint32_t PH[8][2], PL[8][2];
        float ls0 = 0.0f, ls1 = 0.0f;
        #pragma unroll
        for (int ni = 0; ni < 8; ni++) {
            float p0 = __expf(S[ni][0] - mn0);
            float p1 = __expf(S[ni][1] - mn0);
            float p2 = __expf(S[ni][2] - mn1);
            float p3 = __expf(S[ni][3] - mn1);
            ls0 += p0 + p1; ls1 += p2 + p3;
            uint32_t h01 = packh(p0, p1);
            uint32_t h23 = packh(p2, p3);
            PH[ni][0] = h01; PH[ni][1] = h23;
            __half2 hv01 = *(__half2*)&h01;
            __half2 hv23 = *(__half2*)&h23;
            PL[ni][0] = packh(p0 - __half2float(hv01.x), p1 - __half2float(hv01.y));
            PL[ni][1] = packh(p2 - __half2float(hv23.x), p3 - __half2float(hv23.y));
        }
        ls0 += __shfl_xor_sync(0xffffffffu, ls0, 1);
        ls0 += __shfl_xor_sync(0xffffffffu, ls0, 2);
        ls1 += __shfl_xor_sync(0xffffffffu, ls1, 1);
        ls1 += __shfl_xor_sync(0xffffffffu, ls1, 2);
        l0 = l0 * corr0 + ls0;
        l1 = l1 * corr1 + ls1;

        #pragma unroll
        for (int nb = 0; nb < 16; nb++) {
            O[nb][0] *= corr0; O[nb][1] *= corr0;
            O[nb][2] *= corr1; O[nb][3] *= corr1;
        }

        #pragma unroll
        for (int kc = 0; kc < 4; kc++) {
            uint32_t ah2[4] = {PH[2*kc][0], PH[2*kc][1], PH[2*kc+1][0], PH[2*kc+1][1]};
            uint32_t al2[4] = {PL[2*kc][0], PL[2*kc][1], PL[2*kc+1][0], PL[2*kc+1][1]};
            #pragma unroll
            for (int dp = 0; dp < 8; dp++) {
                uint32_t bv[4];
                uint32_t boff = (uint32_t)((dp*16 + b_row) * (AV_RS*2) + b_cb + kc*32);
                ldsm_x4(bv, v_s + boff);
                mma_f16(O[2*dp],   ah2, bv[0], bv[1]);
                mma_f16(O[2*dp],   al2, bv[0], bv[1]);
                mma_f16(O[2*dp+1], ah2, bv[2], bv[3]);
                mma_f16(O[2*dp+1], al2, bv[2], bv[3]);
            }
        }
    }

    float inv0 = 1.0f / l0, inv1 = 1.0f / l1;
    #pragma unroll
    for (int nb = 0; nb < 16; nb++) {
        int col = h*HD + nb*8 + 2*(lane & 3);
        size_t o0 = ((size_t)(b*SEQ) + r0g) * EMBED + col;
        size_t o1 = ((size_t)(b*SEQ) + r1g) * EMBED + col;
        store_h2g(Oh, o0, O[nb][0]*inv0, O[nb][1]*inv0);
        store_h2g(Oh, o1, O[nb][2]*inv1, O[nb][3]*inv1);
    }
}

// ================= launcher ====================================================
extern "C" void kernel_launch(void* const* d_in, const int* in_sizes, int n_in,
                              void* d_out, int out_size)
{
    const float* x      = (const float*)d_in[0];
    const float* freqs  = (const float*)d_in[2];
    const float* w_qkv  = (const float*)d_in[4];
    const float* w_fc   = (const float*)d_in[5];
    const float* w1     = (const float*)d_in[6];
    const float* w2     = (const float*)d_in[7];
    const float* w3     = (const float*)d_in[8];
    const float* attn_w = (const float*)d_in[9];
    const float* ff_w   = (const float*)d_in[10];
    float* out = (float*)d_out;

    float *qkv, *h2, *ff1;
    __half *nbuf, *abuf, *fbuf, *qb, *kb, *vb;
    __half *wqh, *wql, *wfh, *wfl, *w1h, *w1l, *w2h, *w2l, *w3h, *w3l;
    cudaGetSymbolAddress((void**)&qkv,  g_qkv);
    cudaGetSymbolAddress((void**)&h2,   g_h2);
    cudaGetSymbolAddress((void**)&ff1,  g_ff1);
    cudaGetSymbolAddress((void**)&nbuf, g_n);
    cudaGetSymbolAddress((void**)&abuf, g_a);
    cudaGetSymbolAddress((void**)&fbuf, g_f);
    cudaGetSymbolAddress((void**)&qb,   g_q);
    cudaGetSymbolAddress((void**)&kb,   g_k);
    cudaGetSymbolAddress((void**)&vb,   g_v);
    cudaGetSymbolAddress((void**)&wqh,  g_wqkv_h); cudaGetSymbolAddress((void**)&wql, g_wqkv_l);
    cudaGetSymbolAddress((void**)&wfh,  g_wfc_h);  cudaGetSymbolAddress((void**)&wfl, g_wfc_l);
    cudaGetSymbolAddress((void**)&w1h,  g_w1_h);   cudaGetSymbolAddress((void**)&w1l, g_w1_l);
    cudaGetSymbolAddress((void**)&w2h,  g_w2_h);   cudaGetSymbolAddress((void**)&w2l, g_w2_l);
    cudaGetSymbolAddress((void**)&w3h,  g_w3_h);   cudaGetSymbolAddress((void**)&w3l, g_w3_l);

    cudaFuncSetAttribute((const void*)attn_hmma,
                         cudaFuncAttributeMaxDynamicSharedMemorySize, ATTN_SMEM);
    cudaFuncSetAttribute((const void*)hmma_gemm<0>,
                         cudaFuncAttributeMaxDynamicSharedMemorySize, GEMM_SMEM);
    cudaFuncSetAttribute((const void*)hmma_gemm<1>,
                         cudaFuncAttributeMaxDynamicSharedMemorySize, GEMM_SMEM);
    cudaFuncSetAttribute((const void*)hmma_gemm<2>,
                         cudaFuncAttributeMaxDynamicSharedMemorySize, GEMM_SMEM);
    cudaFuncSetAttribute((const void*)hmma_gemm<3>,
                         cudaFuncAttributeMaxDynamicSharedMemorySize, GEMM_SMEM);

    // weight hi/lo fp16 conversion
    cvt_hl_f16<<<(QKV_N*EMBED/4 + 255)/256, 256>>>(w_qkv, wqh, wql, QKV_N*EMBED/4);
    cvt_hl_f16<<<(EMBED*EMBED/4 + 255)/256, 256>>>(w_fc,  wfh, wfl, EMBED*EMBED/4);
    cvt_hl_f16<<<(FF*EMBED/4 + 255)/256, 256>>>(w1, w1h, w1l, FF*EMBED/4);
    cvt_hl_f16<<<(FF*EMBED/4 + 255)/256, 256>>>(w2, w2h, w2l, FF*EMBED/4);
    cvt_hl_f16<<<(EMBED*FF/4 + 255)/256, 256>>>(w3, w3h, w3l, EMBED*FF/4);

    // 1) g = rmsnorm(x) -> fp16
    rmsnorm_h<<<ROWS, 256>>>(x, attn_w, nbuf);
    // 2) qkv GEMM with fused RoPE (Q,K fp16 head-major) ; V -> fp32 qkv
    hmma_gemm<2><<<dim3(QKV_N/128, ROWS/128), 256, GEMM_SMEM>>>(
        nbuf, wqh, wql, qkv, freqs, nullptr, qb, kb, ROWS, QKV_N, EMBED);
    // 3) V transpose -> fp16
    v_split_t<<<dim3(SEQ/32, HD/32, BATCH*NKV), 256>>>(qkv, vb);
    // 4) attention -> fp16
    attn_hmma<<<dim3(SEQ/128, NH, BATCH), 256, ATTN_SMEM>>>(qb, kb, vb, abuf);
    // 5) h2 = x + attn @ w_fc^T
    hmma_gemm<1><<<dim3(EMBED/128, ROWS/128), 256, GEMM_SMEM>>>(
        abuf, wfh, wfl, h2, x, nullptr, nullptr, nullptr, ROWS, EMBED, EMBED);
    // 6) g2 = rmsnorm(h2) -> fp16
    rmsnorm_h<<<ROWS, 256>>>(h2, ff_w, nbuf);
    // 7) ff1 = g2 @ w1^T (fp32)
    hmma_gemm<0><<<dim3(FF/128, ROWS/128), 256, GEMM_SMEM>>>(
        nbuf, w1h, w1l, ff1, nullptr, nullptr, nullptr, nullptr, ROWS, FF, EMBED);
    // 8) ff = silu(ff1) * (g2 @ w2^T) -> fp16
    hmma_gemm<3><<<dim3(FF/128, ROWS/128), 256, GEMM_SMEM>>>(
        nbuf, w2h, w2l, nullptr, ff1, fbuf, nullptr, nullptr, ROWS, FF, EMBED);
    // 9) out = h2 + ff @ w3^T
    hmma_gemm<1><<<dim3(EMBED/128, ROWS/128), 256, GEMM_SMEM>>>(
        fbuf, w3h, w3l, out, h2, nullptr, nullptr, nullptr, ROWS, EMBED, FF);
}

// round 10
// speedup vs baseline: 2.2485x; 1.5736x over previous
#include <cuda_runtime.h>
#include <cuda_fp16.h>
#include <math.h>
#include <cstdint>

// Problem constants
#define BATCH 2
#define SEQ   2048
#define EMBED 2048
#define NH    16
#define NKV   4
#define HD    128
#define FF    5632
#define ROWS  (BATCH*SEQ)          // 4096
#define QKV_N ((NH + 2*NKV)*HD)    // 3072

// ================= scratch (static device globals) =============================
__device__ float g_qkv [ROWS*QKV_N];   // only V columns written (fused qkv epilogue)
__device__ float g_h2  [ROWS*EMBED];
__device__ float g_ff1 [ROWS*FF];
__device__ __half g_n [ROWS*EMBED];          // rmsnorm out (fp16)
__device__ __half g_a [ROWS*EMBED];          // attention out
__device__ __half g_f [ROWS*FF];             // silu*mul out
__device__ __half g_q [ROWS*NH*HD];          // head-major Q (roped)
__device__ __half g_k [ROWS*NKV*HD];         // head-major K (roped)
__device__ __half g_v [ROWS*NKV*HD];         // V transposed [b,kh,d,s]
__device__ __half g_wqkv[QKV_N*EMBED];
__device__ __half g_wfc [EMBED*EMBED];
__device__ __half g_w1  [FF*EMBED];
__device__ __half g_w2  [FF*EMBED];
__device__ __half g_w3  [EMBED*FF];

// ================= helpers =====================================================
__device__ __forceinline__ float silu_f(float z) { return z / (1.0f + __expf(-z)); }

__device__ __forceinline__ uint32_t smem_u32(const void* p) {
    uint32_t a;
    asm("{ .reg .u64 t; cvta.to.shared.u64 t, %1; cvt.u32.u64 %0, t; }" : "=r"(a) : "l"(p));
    return a;
}
__device__ __forceinline__ void cpa16(uint32_t so, const void* ga) {
    asm volatile("cp.async.cg.shared.global [%0], [%1], 16;\n" :: "r"(so), "l"(ga));
}
__device__ __forceinline__ void ldsm_x4(uint32_t (&r)[4], uint32_t addr) {
    asm volatile("ldmatrix.sync.aligned.m8n8.x4.shared.b16 {%0,%1,%2,%3}, [%4];"
                 : "=r"(r[0]), "=r"(r[1]), "=r"(r[2]), "=r"(r[3]) : "r"(addr));
}
__device__ __forceinline__ void mma_f16(float (&d)[4], const uint32_t (&a)[4],
                                        uint32_t b0, uint32_t b1) {
    asm volatile(
        "mma.sync.aligned.m16n8k16.row.col.f32.f16.f16.f32 "
        "{%0,%1,%2,%3}, {%4,%5,%6,%7}, {%8,%9}, {%0,%1,%2,%3};"
        : "+f"(d[0]), "+f"(d[1]), "+f"(d[2]), "+f"(d[3])
        : "r"(a[0]), "r"(a[1]), "r"(a[2]), "r"(a[3]), "r"(b0), "r"(b1));
}
// pack two fp32 -> f16x2 (first arg -> low half)
__device__ __forceinline__ uint32_t packh(float lo, float hi) {
    uint32_t d;
    asm("cvt.rn.f16x2.f32 %0, %1, %2;" : "=r"(d) : "f"(hi), "f"(lo));
    return d;
}
__device__ __forceinline__ void store_h2g(__half* __restrict__ p, size_t idx,
                                          float a, float b) {
    __half2 v; v.x = __float2half_rn(a); v.y = __float2half_rn(b);
    *(__half2*)(p + idx) = v;
}
__device__ __forceinline__ void store_h4g(__half* __restrict__ p, size_t idx,
                                          float a, float b, float c, float d) {
    __half2 v0, v1;
    v0.x = __float2half_rn(a); v0.y = __float2half_rn(b);
    v1.x = __float2half_rn(c); v1.y = __float2half_rn(d);
    *(__half2*)(p + idx)     = v0;
    *(__half2*)(p + idx + 2) = v1;
}

// fp32 -> fp16 (weights prepass)
__global__ __launch_bounds__(256) void cvt_h(
    const float* __restrict__ src, __half* __restrict__ dst, int n4)
{
    int i = blockIdx.x * 256 + threadIdx.x;
    if (i >= n4) return;
    float4 v = ((const float4*)src)[i];
    store_h4g(dst, (size_t)i * 4, v.x, v.y, v.z, v.w);
}

// rmsnorm with fp16 output
__global__ __launch_bounds__(256) void rmsnorm_h(
    const float* __restrict__ x, const float* __restrict__ w,
    __half* __restrict__ o)
{
    int row = blockIdx.x;
    const float4* xr = (const float4*)(x + (size_t)row * EMBED);
    int t = threadIdx.x;
    float4 v0 = xr[t];
    float4 v1 = xr[t + 256];
    float ss = v0.x*v0.x + v0.y*v0.y + v0.z*v0.z + v0.w*v0.w
             + v1.x*v1.x + v1.y*v1.y + v1.z*v1.z + v1.w*v1.w;
    #pragma unroll
    for (int m = 16; m; m >>= 1) ss += __shfl_xor_sync(0xffffffffu, ss, m);
    __shared__ float red[8];
    if ((t & 31) == 0) red[t >> 5] = ss;
    __syncthreads();
    float tot = red[0]+red[1]+red[2]+red[3]+red[4]+red[5]+red[6]+red[7];
    float r = rsqrtf(tot * (1.0f/EMBED) + 1e-5f);
    const float4* wr = (const float4*)w;
    float4 w0 = wr[t], w1 = wr[t + 256];
    size_t base = (size_t)row * EMBED;
    store_h4g(o, base + t*4,        v0.x*r*w0.x, v0.y*r*w0.y, v0.z*r*w0.z, v0.w*r*w0.w);
    store_h4g(o, base + 1024 + t*4, v1.x*r*w1.x, v1.y*r*w1.y, v1.z*r*w1.z, v1.w*r*w1.w);
}

// ---------------- V: transpose to [b,kh,d,s] + fp16 ---------------------------
__global__ __launch_bounds__(256) void v_split_t(
    const float* __restrict__ qkv, __half* __restrict__ vh)
{
    __shared__ float tile[32][33];
    int s0 = blockIdx.x * 32, d0 = blockIdx.y * 32;
    int b  = blockIdx.z >> 2, kh = blockIdx.z & 3;
    int tx = threadIdx.x & 31, ty = threadIdx.x >> 5;   // 32 x 8
    #pragma unroll
    for (int i = 0; i < 4; i++) {
        int s = s0 + ty + i*8;
        tile[ty + i*8][tx] = qkv[(size_t)(b*SEQ + s) * QKV_N + (NH+NKV)*HD + kh*HD + d0 + tx];
    }
    __syncthreads();
    #pragma unroll
    for (int i = 0; i < 4; i++) {
        int d = d0 + ty + i*8;
        float v = tile[tx][ty + i*8];
        size_t o = ((size_t)(b*NKV + kh) * HD + d) * SEQ + s0 + tx;
        vh[o] = __float2half_rn(v);
    }
}

// ================= HMMA fp16 GEMM (single product) =============================
// C[M,N] = A[M,K] @ W[N,K]^T ; A, W single fp16.
// EPI 0: Cf = acc
// EPI 1: Cf = acc + X
// EPI 2: qkv fused: Q/K heads -> RoPE fp16 head-major (X = freqs); V -> fp32 Cf
// EPI 3: Ch = fp16(acc * silu(X))
#define BKC      32
#define RS       40
#define TILE_PB  (128*RS*2)            // 10240
#define STAGE_B  (2*TILE_PB)           // A, W
#define NSTAGE   2
#define GEMM_SMEM (NSTAGE*STAGE_B)     // 40960

__device__ __forceinline__ void load_stage(
    uint32_t sb, int stage, int chunk, int tid,
    const __half* __restrict__ A, const __half* __restrict__ B0, int K)
{
    const __half* mats[2] = {A, B0};
    uint32_t stage_base = sb + (uint32_t)stage * STAGE_B;
    #pragma unroll
    for (int m = 0; m < 2; m++) {
        const __half* gp = mats[m] + chunk * BKC;
        uint32_t tb = stage_base + m * TILE_PB;
        #pragma unroll
        for (int it = 0; it < 2; it++) {
            int ch = it * 256 + tid;
            int r  = ch >> 2;
            int cc = ch & 3;
            uint32_t so = tb + (uint32_t)(r * (RS*2) + cc * 16);
            cpa16(so, gp + (size_t)r * K + cc * 8);
        }
    }
}

template<int EPI>
__global__ __launch_bounds__(256, 2) void hmma_gemm(
    const __half* __restrict__ A, const __half* __restrict__ Bh,
    float* __restrict__ Cf, const float* __restrict__ X,
    __half* __restrict__ Ch,
    __half* __restrict__ Qo, __half* __restrict__ Ko,
    int M, int N, int K)
{
    extern __shared__ char smem[];
    uint32_t sb = smem_u32(smem);
    const int tid  = threadIdx.x;
    const int wid  = tid >> 5;
    const int lane = tid & 31;
    const int bx = blockIdx.x, by = blockIdx.y;
    const int wm = (wid >> 2) * 64;
    const int wn = (wid & 3) * 32;

    const __half* A0 = A  + (size_t)by * 128 * K;
    const __half* B0 = Bh + (size_t)bx * 128 * K;

    float d[4][4][4];
    #pragma unroll
    for (int i = 0; i < 4; i++)
        #pragma unroll
        for (int j = 0; j < 4; j++)
            #pragma unroll
            for (int r = 0; r < 4; r++) d[i][j][r] = 0.0f;

    const int a_row = lane & 15;
    const int a_cb  = (lane >> 4) * 16;
    const int b_row = (lane & 7) | ((lane >> 1) & 8);
    const int b_cb  = ((lane >> 3) & 1) * 16;

    const int NC = K / BKC;

    load_stage(sb, 0, 0, tid, A0, B0, K);
    asm volatile("cp.async.commit_group;\n" ::: "memory");

    for (int c = 0; c < NC; c++) {
        if (c + 1 < NC)
            load_stage(sb, (c + 1) & 1, c + 1, tid, A0, B0, K);
        asm volatile("cp.async.commit_group;\n" ::: "memory");
        asm volatile("cp.async.wait_group 1;\n" ::: "memory");
        __syncthreads();

        uint32_t st = sb + (uint32_t)(c & 1) * STAGE_B;
        uint32_t a_b  = st;
        uint32_t bh_b = st + TILE_PB;

        #pragma unroll
        for (int ks = 0; ks < 2; ks++) {
            uint32_t bh2[2][4];
            #pragma unroll
            for (int nb = 0; nb < 2; nb++) {
                uint32_t boff = (uint32_t)((wn + nb*16 + b_row) * (RS*2) + b_cb + ks*32);
                ldsm_x4(bh2[nb], bh_b + boff);
            }
            #pragma unroll
            for (int mi = 0; mi < 4; mi++) {
                uint32_t av[4];
                uint32_t aoff = (uint32_t)((wm + mi*16 + a_row) * (RS*2) + a_cb + ks*32);
                ldsm_x4(av, a_b + aoff);
                #pragma unroll
                for (int ni = 0; ni < 4; ni++) {
                    int nb = ni >> 1, hf = (ni & 1) * 2;
                    mma_f16(d[mi][ni], av, bh2[nb][hf], bh2[nb][hf+1]);
                }
            }
        }
        __syncthreads();
    }

    const int q  = lane >> 2;
    const int tq = lane & 3;
    #pragma unroll
    for (int mi = 0; mi < 4; mi++) {
        int row0 = by*128 + wm + mi*16 + q;
        #pragma unroll
        for (int ni = 0; ni < 4; ni++) {
            int col = bx*128 + wn + ni*8 + tq*2;
            size_t off0 = (size_t)row0 * N + col;
            size_t off1 = off0 + (size_t)8 * N;
            float v0 = d[mi][ni][0], v1 = d[mi][ni][1];
            float v2 = d[mi][ni][2], v3 = d[mi][ni][3];
            if (EPI == 0) {
                *(float2*)(Cf + off0) = make_float2(v0, v1);
                *(float2*)(Cf + off1) = make_float2(v2, v3);
            } else if (EPI == 1) {
                float2 x0 = *(const float2*)(X + off0);
                float2 x1 = *(const float2*)(X + off1);
                *(float2*)(Cf + off0) = make_float2(v0 + x0.x, v1 + x0.y);
                *(float2*)(Cf + off1) = make_float2(v2 + x1.x, v3 + x1.y);
            } else if (EPI == 2) {
                // bx tile == one head (HD == 128). X = freqs table (S, HD/2, 2).
                int head = bx;
                if (head < NH + NKV) {
                    int cl = wn + ni*8 + tq*2;
                    int r0 = row0, r1 = row0 + 8;
                    int b0 = r0 >> 11;
                    int s0 = r0 & (SEQ-1), s1 = r1 & (SEQ-1);
                    float2 f0 = *(const float2*)(X + (size_t)s0*HD + cl);
                    float2 f1 = *(const float2*)(X + (size_t)s1*HD + cl);
                    float n00 = v0*f0.x - v1*f0.y, n01 = v1*f0.x + v0*f0.y;
                    float n10 = v2*f1.x - v3*f1.y, n11 = v3*f1.x + v2*f1.y;
                    if (head < NH) {
                        size_t o0 = ((size_t)(b0*NH + head)*SEQ + s0)*HD + cl;
                        size_t o1 = ((size_t)(b0*NH + head)*SEQ + s1)*HD + cl;
                        store_h2g(Qo, o0, n00, n01);
                        store_h2g(Qo, o1, n10, n11);
                    } else {
                        int kh = head - NH;
                        size_t o0 = ((size_t)(b0*NKV + kh)*SEQ + s0)*HD + cl;
                        size_t o1 = ((size_t)(b0*NKV + kh)*SEQ + s1)*HD + cl;
                        store_h2g(Ko, o0, n00, n01);
                        store_h2g(Ko, o1, n10, n11);
                    }
                } else {
                    *(float2*)(Cf + off0) = make_float2(v0, v1);
                    *(float2*)(Cf + off1) = make_float2(v2, v3);
                }
            } else {  // EPI 3
                float2 x0 = *(const float2*)(X + off0);
                float2 x1 = *(const float2*)(X + off1);
                store_h2g(Ch, off0, v0 * silu_f(x0.x), v1 * silu_f(x0.y));
                store_h2g(Ch, off1, v2 * silu_f(x1.x), v3 * silu_f(x1.y));
            }
        }
    }
}

// ================= HMMA flash attention (fp16, causal, GQA) ====================
// Q,K,V,P all single fp16 products.
#define AQ_RS   136
#define AV_RS   72
#define AQT_B   (128*AQ_RS*2)    // 34816
#define AKT_B   (64*AQ_RS*2)     // 17408
#define AVT_B   (128*AV_RS*2)    // 18432
#define ATTN_SMEM (AQT_B + AKT_B + AVT_B)   // 70656

__global__ __launch_bounds__(256, 2) void attn_hmma(
    const __half* __restrict__ Q, const __half* __restrict__ Kg,
    const __half* __restrict__ Vg, __half* __restrict__ Oh)
{
    extern __shared__ char smem[];
    uint32_t sb = smem_u32(smem);
    uint32_t q_s = sb;
    uint32_t k_s = sb + AQT_B;
    uint32_t v_s = k_s + AKT_B;

    const int tid = threadIdx.x, wid = tid >> 5, lane = tid & 31;
    const int bx = blockIdx.x, h = blockIdx.y, b = blockIdx.z;
    const int kvh = h >> 2;
    const int q0 = bx * 128;

    const __half* gQ = Q  + ((size_t)(b*NH + h) * SEQ + q0) * HD;
    const __half* gK = Kg + (size_t)(b*NKV + kvh) * SEQ * HD;
    const __half* gV = Vg + (size_t)(b*NKV + kvh) * HD * SEQ;

    #pragma unroll
    for (int i = 0; i < 8; i++) {
        int ch = i * 256 + tid;
        int r = ch >> 4, cc = ch & 15;
        uint32_t so = (uint32_t)(r * (AQ_RS*2) + cc * 16);
        cpa16(q_s + so, gQ + (size_t)r * HD + cc * 8);
    }
    asm volatile("cp.async.commit_group;\n" ::: "memory");

    float O[16][4];
    #pragma unroll
    for (int i = 0; i < 16; i++)
        #pragma unroll
        for (int j = 0; j < 4; j++) O[i][j] = 0.0f;
    float m0 = -1e30f, m1 = -1e30f, l0 = 0.0f, l1 = 0.0f;

    const int a_row = lane & 15;
    const int a_cb  = (lane >> 4) * 16;
    const int b_row = (lane & 7) | ((lane >> 1) & 8);
    const int b_cb  = ((lane >> 3) & 1) * 16;
    const int r0g = q0 + wid*16 + (lane >> 2);
    const int r1g = r0g + 8;
    const float scale = rsqrtf((float)EMBED);

    const int ktiles = 2*bx + 2;
    for (int kt = 0; kt < ktiles; kt++) {
        int k0 = kt * 64;
        __syncthreads();
        #pragma unroll
        for (int i = 0; i < 4; i++) {
            int ch = i * 256 + tid;
            int r = ch >> 4, cc = ch & 15;
            uint32_t so = (uint32_t)(r * (AQ_RS*2) + cc * 16);
            cpa16(k_s + so, gK + (size_t)(k0 + r) * HD + cc * 8);
        }
        #pragma unroll
        for (int i = 0; i < 4; i++) {
            int ch = i * 256 + tid;
            int r = ch >> 3, cc = ch & 7;
            uint32_t so = (uint32_t)(r * (AV_RS*2) + cc * 16);
            cpa16(v_s + so, gV + (size_t)r * SEQ + k0 + cc * 8);
        }
        asm volatile("cp.async.commit_group;\n" ::: "memory");
        asm volatile("cp.async.wait_group 0;\n" ::: "memory");
        __syncthreads();

        float S[8][4];
        #pragma unroll
        for (int i = 0; i < 8; i++)
            #pragma unroll
            for (int j = 0; j < 4; j++) S[i][j] = 0.0f;

        #pragma unroll
        for (int kk = 0; kk < 8; kk++) {
            uint32_t av[4];
            uint32_t aoff = (uint32_t)((wid*16 + a_row) * (AQ_RS*2) + a_cb + kk*32);
            ldsm_x4(av, q_s + aoff);
            #pragma unroll
            for (int np = 0; np < 4; np++) {
                uint32_t bv[4];
                uint32_t boff = (uint32_t)((np*16 + b_row) * (AQ_RS*2) + b_cb + kk*32);
                ldsm_x4(bv, k_s + boff);
                mma_f16(S[2*np],   av, bv[0], bv[1]);
                mma_f16(S[2*np+1], av, bv[2], bv[3]);
            }
        }

        #pragma unroll
        for (int ni = 0; ni < 8; ni++) {
            int c0 = k0 + ni*8 + 2*(lane & 3);
            S[ni][0] = (c0     > r0g) ? -1e30f : S[ni][0] * scale;
            S[ni][1] = (c0 + 1 > r0g) ? -1e30f : S[ni][1] * scale;
            S[ni][2] = (c0     > r1g) ? -1e30f : S[ni][2] * scale;
            S[ni][3] = (c0 + 1 > r1g) ? -1e30f : S[ni][3] * scale;
        }

        float mx0 = -1e30f, mx1 = -1e30f;
        #pragma unroll
        for (int ni = 0; ni < 8; ni++) {
            mx0 = fmaxf(mx0, fmaxf(S[ni][0], S[ni][1]));
            mx1 = fmaxf(mx1, fmaxf(S[ni][2], S[ni][3]));
        }
        mx0 = fmaxf(mx0, __shfl_xor_sync(0xffffffffu, mx0, 1));
        mx0 = fmaxf(mx0, __shfl_xor_sync(0xffffffffu, mx0, 2));
        mx1 = fmaxf(mx1, __shfl_xor_sync(0xffffffffu, mx1, 1));
        mx1 = fmaxf(mx1, __shfl_xor_sync(0xffffffffu, mx1, 2));
        float mn0 = fmaxf(m0, mx0), mn1 = fmaxf(m1, mx1);
        float corr0 = __expf(m0 - mn0), corr1 = __expf(m1 - mn1);
        m0 = mn0; m1 = mn1;

        uint32_t PH[8][2];
        float ls0 = 0.0f, ls1 = 0.0f;
        #pragma unroll
        for (int ni = 0; ni < 8; ni++) {
            float p0 = __expf(S[ni][0] - mn0);
            float p1 = __expf(S[ni][1] - mn0);
            float p2 = __expf(S[ni][2] - mn1);
            float p3 = __expf(S[ni][3] - mn1);
            ls0 += p0 + p1; ls1 += p2 + p3;
            PH[ni][0] = packh(p0, p1);
            PH[ni][1] = packh(p2, p3);
        }
        ls0 += __shfl_xor_sync(0xffffffffu, ls0, 1);
        ls0 += __shfl_xor_sync(0xffffffffu, ls0, 2);
        ls1 += __shfl_xor_sync(0xffffffffu, ls1, 1);
        ls1 += __shfl_xor_sync(0xffffffffu, ls1, 2);
        l0 = l0 * corr0 + ls0;
        l1 = l1 * corr1 + ls1;

        #pragma unroll
        for (int nb = 0; nb < 16; nb++) {
            O[nb][0] *= corr0; O[nb][1] *= corr0;
            O[nb][2] *= corr1; O[nb][3] *= corr1;
        }

        #pragma unroll
        for (int kc = 0; kc < 4; kc++) {
            uint32_t ah2[4] = {PH[2*kc][0], PH[2*kc][1], PH[2*kc+1][0], PH[2*kc+1][1]};
            #pragma unroll
            for (int dp = 0; dp < 8; dp++) {
                uint32_t bv[4];
                uint32_t boff = (uint32_t)((dp*16 + b_row) * (AV_RS*2) + b_cb + kc*32);
                ldsm_x4(bv, v_s + boff);
                mma_f16(O[2*dp],   ah2, bv[0], bv[1]);
                mma_f16(O[2*dp+1], ah2, bv[2], bv[3]);
            }
        }
    }

    float inv0 = 1.0f / l0, inv1 = 1.0f / l1;
    #pragma unroll
    for (int nb = 0; nb < 16; nb++) {
        int col = h*HD + nb*8 + 2*(lane & 3);
        size_t o0 = ((size_t)(b*SEQ) + r0g) * EMBED + col;
        size_t o1 = ((size_t)(b*SEQ) + r1g) * EMBED + col;
        store_h2g(Oh, o0, O[nb][0]*inv0, O[nb][1]*inv0);
        store_h2g(Oh, o1, O[nb][2]*inv1, O[nb][3]*inv1);
    }
}

// ================= launcher ====================================================
extern "C" void kernel_launch(void* const* d_in, const int* in_sizes, int n_in,
                              void* d_out, int out_size)
{
    const float* x      = (const float*)d_in[0];
    const float* freqs  = (const float*)d_in[2];
    const float* w_qkv  = (const float*)d_in[4];
    const float* w_fc   = (const float*)d_in[5];
    const float* w1     = (const float*)d_in[6];
    const float* w2     = (const float*)d_in[7];
    const float* w3     = (const float*)d_in[8];
    const float* attn_w = (const float*)d_in[9];
    const float* ff_w   = (const float*)d_in[10];
    float* out = (float*)d_out;

    float *qkv, *h2, *ff1;
    __half *nbuf, *abuf, *fbuf, *qb, *kb, *vb;
    __half *wq, *wf, *w1b, *w2b, *w3b;
    cudaGetSymbolAddress((void**)&qkv,  g_qkv);
    cudaGetSymbolAddress((void**)&h2,   g_h2);
    cudaGetSymbolAddress((void**)&ff1,  g_ff1);
    cudaGetSymbolAddress((void**)&nbuf, g_n);
    cudaGetSymbolAddress((void**)&abuf, g_a);
    cudaGetSymbolAddress((void**)&fbuf, g_f);
    cudaGetSymbolAddress((void**)&qb,   g_q);
    cudaGetSymbolAddress((void**)&kb,   g_k);
    cudaGetSymbolAddress((void**)&vb,   g_v);
    cudaGetSymbolAddress((void**)&wq,   g_wqkv);
    cudaGetSymbolAddress((void**)&wf,   g_wfc);
    cudaGetSymbolAddress((void**)&w1b,  g_w1);
    cudaGetSymbolAddress((void**)&w2b,  g_w2);
    cudaGetSymbolAddress((void**)&w3b,  g_w3);

    cudaFuncSetAttribute((const void*)attn_hmma,
                         cudaFuncAttributeMaxDynamicSharedMemorySize, ATTN_SMEM);
    cudaFuncSetAttribute((const void*)hmma_gemm<0>,
                         cudaFuncAttributeMaxDynamicSharedMemorySize, GEMM_SMEM);
    cudaFuncSetAttribute((const void*)hmma_gemm<1>,
                         cudaFuncAttributeMaxDynamicSharedMemorySize, GEMM_SMEM);
    cudaFuncSetAttribute((const void*)hmma_gemm<2>,
                         cudaFuncAttributeMaxDynamicSharedMemorySize, GEMM_SMEM);
    cudaFuncSetAttribute((const void*)hmma_gemm<3>,
                         cudaFuncAttributeMaxDynamicSharedMemorySize, GEMM_SMEM);

    // weight fp16 conversion
    cvt_h<<<(QKV_N*EMBED/4 + 255)/256, 256>>>(w_qkv, wq, QKV_N*EMBED/4);
    cvt_h<<<(EMBED*EMBED/4 + 255)/256, 256>>>(w_fc, wf, EMBED*EMBED/4);
    cvt_h<<<(FF*EMBED/4 + 255)/256, 256>>>(w1, w1b, FF*EMBED/4);
    cvt_h<<<(FF*EMBED/4 + 255)/256, 256>>>(w2, w2b, FF*EMBED/4);
    cvt_h<<<(EMBED*FF/4 + 255)/256, 256>>>(w3, w3b, EMBED*FF/4);

    // 1) g = rmsnorm(x) -> fp16
    rmsnorm_h<<<ROWS, 256>>>(x, attn_w, nbuf);
    // 2) qkv GEMM with fused RoPE (Q,K fp16 head-major) ; V -> fp32 qkv
    hmma_gemm<2><<<dim3(QKV_N/128, ROWS/128), 256, GEMM_SMEM>>>(
        nbuf, wq, qkv, freqs, nullptr, qb, kb, ROWS, QKV_N, EMBED);
    // 3) V transpose -> fp16
    v_split_t<<<dim3(SEQ/32, HD/32, BATCH*NKV), 256>>>(qkv, vb);
    // 4) attention -> fp16
    attn_hmma<<<dim3(SEQ/128, NH, BATCH), 256, ATTN_SMEM>>>(qb, kb, vb, abuf);
    // 5) h2 = x + attn @ w_fc^T
    hmma_gemm<1><<<dim3(EMBED/128, ROWS/128), 256, GEMM_SMEM>>>(
        abuf, wf, h2, x, nullptr, nullptr, nullptr, ROWS, EMBED, EMBED);
    // 6) g2 = rmsnorm(h2) -> fp16
    rmsnorm_h<<<ROWS, 256>>>(h2, ff_w, nbuf);
    // 7) ff1 = g2 @ w1^T (fp32)
    hmma_gemm<0><<<dim3(FF/128, ROWS/128), 256, GEMM_SMEM>>>(
        nbuf, w1b, ff1, nullptr, nullptr, nullptr, nullptr, ROWS, FF, EMBED);
    // 8) ff = silu(ff1) * (g2 @ w2^T) -> fp16
    hmma_gemm<3><<<dim3(FF/128, ROWS/128), 256, GEMM_SMEM>>>(
        nbuf, w2b, nullptr, ff1, fbuf, nullptr, nullptr, ROWS, FF, EMBED);
    // 9) out = h2 + ff @ w3^T
    hmma_gemm<1><<<dim3(EMBED/128, ROWS/128), 256, GEMM_SMEM>>>(
        fbuf, w3b, out, h2, nullptr, nullptr, nullptr, ROWS, EMBED, FF);
}

// round 12
// speedup vs baseline: 2.5964x; 1.1547x over previous
#include <cuda_runtime.h>
#include <cuda_fp16.h>
#include <math.h>
#include <cstdint>

// Problem constants
#define BATCH 2
#define SEQ   2048
#define EMBED 2048
#define NH    16
#define NKV   4
#define HD    128
#define FF    5632
#define ROWS  (BATCH*SEQ)          // 4096
#define QKV_N ((NH + 2*NKV)*HD)    // 3072

// ================= scratch (static device globals) =============================
__device__ float g_qkv [ROWS*QKV_N];   // only V columns written (fused qkv epilogue)
__device__ float g_h2  [ROWS*EMBED];
__device__ __half g_ff1[ROWS*FF];            // w1 output (fp16)
__device__ __half g_n [ROWS*EMBED];          // rmsnorm out (fp16)
__device__ __half g_a [ROWS*EMBED];          // attention out
__device__ __half g_f [ROWS*FF];             // silu*mul out
__device__ __half g_q [ROWS*NH*HD];          // head-major Q (roped)
__device__ __half g_k [ROWS*NKV*HD];         // head-major K (roped)
__device__ __half g_v [ROWS*NKV*HD];         // V transposed [b,kh,d,s]
__device__ __half g_wqkv[QKV_N*EMBED];
__device__ __half g_wfc [EMBED*EMBED];
__device__ __half g_w1  [FF*EMBED];
__device__ __half g_w2  [FF*EMBED];
__device__ __half g_w3  [EMBED*FF];

// ================= helpers =====================================================
__device__ __forceinline__ float silu_f(float z) { return z / (1.0f + __expf(-z)); }

__device__ __forceinline__ uint32_t smem_u32(const void* p) {
    uint32_t a;
    asm("{ .reg .u64 t; cvta.to.shared.u64 t, %1; cvt.u32.u64 %0, t; }" : "=r"(a) : "l"(p));
    return a;
}
__device__ __forceinline__ void cpa16(uint32_t so, const void* ga) {
    asm volatile("cp.async.cg.shared.global [%0], [%1], 16;\n" :: "r"(so), "l"(ga));
}
__device__ __forceinline__ void ldsm_x4(uint32_t (&r)[4], uint32_t addr) {
    asm volatile("ldmatrix.sync.aligned.m8n8.x4.shared.b16 {%0,%1,%2,%3}, [%4];"
                 : "=r"(r[0]), "=r"(r[1]), "=r"(r[2]), "=r"(r[3]) : "r"(addr));
}
__device__ __forceinline__ void mma_f16(float (&d)[4], const uint32_t (&a)[4],
                                        uint32_t b0, uint32_t b1) {
    asm volatile(
        "mma.sync.aligned.m16n8k16.row.col.f32.f16.f16.f32 "
        "{%0,%1,%2,%3}, {%4,%5,%6,%7}, {%8,%9}, {%0,%1,%2,%3};"
        : "+f"(d[0]), "+f"(d[1]), "+f"(d[2]), "+f"(d[3])
        : "r"(a[0]), "r"(a[1]), "r"(a[2]), "r"(a[3]), "r"(b0), "r"(b1));
}
// pack two fp32 -> f16x2 (first arg -> low half)
__device__ __forceinline__ uint32_t packh(float lo, float hi) {
    uint32_t d;
    asm("cvt.rn.f16x2.f32 %0, %1, %2;" : "=r"(d) : "f"(hi), "f"(lo));
    return d;
}
__device__ __forceinline__ void store_h2g(__half* __restrict__ p, size_t idx,
                                          float a, float b) {
    __half2 v; v.x = __float2half_rn(a); v.y = __float2half_rn(b);
    *(__half2*)(p + idx) = v;
}
__device__ __forceinline__ void store_h4g(__half* __restrict__ p, size_t idx,
                                          float a, float b, float c, float d) {
    __half2 v0, v1;
    v0.x = __float2half_rn(a); v0.y = __float2half_rn(b);
    v1.x = __float2half_rn(c); v1.y = __float2half_rn(d);
    *(__half2*)(p + idx)     = v0;
    *(__half2*)(p + idx + 2) = v1;
}

// fp32 -> fp16 (weights prepass)
__global__ __launch_bounds__(256) void cvt_h(
    const float* __restrict__ src, __half* __restrict__ dst, int n4)
{
    int i = blockIdx.x * 256 + threadIdx.x;
    if (i >= n4) return;
    float4 v = ((const float4*)src)[i];
    store_h4g(dst, (size_t)i * 4, v.x, v.y, v.z, v.w);
}

// rmsnorm with fp16 output
__global__ __launch_bounds__(256) void rmsnorm_h(
    const float* __restrict__ x, const float* __restrict__ w,
    __half* __restrict__ o)
{
    int row = blockIdx.x;
    const float4* xr = (const float4*)(x + (size_t)row * EMBED);
    int t = threadIdx.x;
    float4 v0 = xr[t];
    float4 v1 = xr[t + 256];
    float ss = v0.x*v0.x + v0.y*v0.y + v0.z*v0.z + v0.w*v0.w
             + v1.x*v1.x + v1.y*v1.y + v1.z*v1.z + v1.w*v1.w;
    #pragma unroll
    for (int m = 16; m; m >>= 1) ss += __shfl_xor_sync(0xffffffffu, ss, m);
    __shared__ float red[8];
    if ((t & 31) == 0) red[t >> 5] = ss;
    __syncthreads();
    float tot = red[0]+red[1]+red[2]+red[3]+red[4]+red[5]+red[6]+red[7];
    float r = rsqrtf(tot * (1.0f/EMBED) + 1e-5f);
    const float4* wr = (const float4*)w;
    float4 w0 = wr[t], w1 = wr[t + 256];
    size_t base = (size_t)row * EMBED;
    store_h4g(o, base + t*4,        v0.x*r*w0.x, v0.y*r*w0.y, v0.z*r*w0.z, v0.w*r*w0.w);
    store_h4g(o, base + 1024 + t*4, v1.x*r*w1.x, v1.y*r*w1.y, v1.z*r*w1.z, v1.w*r*w1.w);
}

// ---------------- V: transpose to [b,kh,d,s] + fp16 ---------------------------
__global__ __launch_bounds__(256) void v_split_t(
    const float* __restrict__ qkv, __half* __restrict__ vh)
{
    __shared__ float tile[32][33];
    int s0 = blockIdx.x * 32, d0 = blockIdx.y * 32;
    int b  = blockIdx.z >> 2, kh = blockIdx.z & 3;
    int tx = threadIdx.x & 31, ty = threadIdx.x >> 5;   // 32 x 8
    #pragma unroll
    for (int i = 0; i < 4; i++) {
        int s = s0 + ty + i*8;
        tile[ty + i*8][tx] = qkv[(size_t)(b*SEQ + s) * QKV_N + (NH+NKV)*HD + kh*HD + d0 + tx];
    }
    __syncthreads();
    #pragma unroll
    for (int i = 0; i < 4; i++) {
        int d = d0 + ty + i*8;
        float v = tile[tx][ty + i*8];
        size_t o = ((size_t)(b*NKV + kh) * HD + d) * SEQ + s0 + tx;
        vh[o] = __float2half_rn(v);
    }
}

// ================= HMMA fp16 GEMM (single product, BK=64) ======================
// C[M,N] = A[M,K] @ W[N,K]^T ; A, W single fp16.
// EPI 1: Cf = acc + X (fp32 X)
// EPI 2: qkv fused: Q/K heads -> RoPE fp16 head-major (X = freqs); V -> fp32 Cf
// EPI 3: Ch = fp16(acc * silu(Xh))  (fp16 Xh)
// EPI 5: Ch = fp16(acc)
#define BKC      64
#define RS       72                    // 144B row stride; r*144 mod 128 spans all 8 16B-groups
#define TILE_PB  (128*RS*2)            // 18432
#define STAGE_B  (2*TILE_PB)           // A, W
#define NSTAGE   2
#define GEMM_SMEM (NSTAGE*STAGE_B)     // 73728

__device__ __forceinline__ void load_stage(
    uint32_t sb, int stage, int chunk, int tid,
    const __half* __restrict__ A, const __half* __restrict__ B0, int K)
{
    const __half* mats[2] = {A, B0};
    uint32_t stage_base = sb + (uint32_t)stage * STAGE_B;
    #pragma unroll
    for (int m = 0; m < 2; m++) {
        const __half* gp = mats[m] + chunk * BKC;
        uint32_t tb = stage_base + m * TILE_PB;
        #pragma unroll
        for (int it = 0; it < 4; it++) {
            int ch = it * 256 + tid;        // 0..1023
            int r  = ch >> 3;               // 0..127
            int cc = ch & 7;                // 16B chunk within 128B row
            uint32_t so = tb + (uint32_t)(r * (RS*2) + cc * 16);
            cpa16(so, gp + (size_t)r * K + cc * 8);
        }
    }
}

template<int EPI>
__global__ __launch_bounds__(256, 2) void hmma_gemm(
    const __half* __restrict__ A, const __half* __restrict__ Bh,
    float* __restrict__ Cf, const float* __restrict__ X,
    const __half* __restrict__ Xh, __half* __restrict__ Ch,
    __half* __restrict__ Qo, __half* __restrict__ Ko,
    int M, int N, int K)
{
    extern __shared__ char smem[];
    uint32_t sb = smem_u32(smem);
    const int tid  = threadIdx.x;
    const int wid  = tid >> 5;
    const int lane = tid & 31;
    const int bx = blockIdx.x, by = blockIdx.y;
    const int wm = (wid >> 2) * 64;
    const int wn = (wid & 3) * 32;

    const __half* A0 = A  + (size_t)by * 128 * K;
    const __half* B0 = Bh + (size_t)bx * 128 * K;

    float d[4][4][4];
    #pragma unroll
    for (int i = 0; i < 4; i++)
        #pragma unroll
        for (int j = 0; j < 4; j++)
            #pragma unroll
            for (int r = 0; r < 4; r++) d[i][j][r] = 0.0f;

    const int a_row = lane & 15;
    const int a_cb  = (lane >> 4) * 16;
    const int b_row = (lane & 7) | ((lane >> 1) & 8);
    const int b_cb  = ((lane >> 3) & 1) * 16;

    const int NC = K / BKC;

    load_stage(sb, 0, 0, tid, A0, B0, K);
    asm volatile("cp.async.commit_group;\n" ::: "memory");

    for (int c = 0; c < NC; c++) {
        if (c + 1 < NC)
            load_stage(sb, (c + 1) & 1, c + 1, tid, A0, B0, K);
        asm volatile("cp.async.commit_group;\n" ::: "memory");
        asm volatile("cp.async.wait_group 1;\n" ::: "memory");
        __syncthreads();

        uint32_t st = sb + (uint32_t)(c & 1) * STAGE_B;
        uint32_t a_b  = st;
        uint32_t bh_b = st + TILE_PB;

        #pragma unroll
        for (int ks = 0; ks < 4; ks++) {
            uint32_t bh2[2][4];
            #pragma unroll
            for (int nb = 0; nb < 2; nb++) {
                uint32_t boff = (uint32_t)((wn + nb*16 + b_row) * (RS*2) + b_cb + ks*32);
                ldsm_x4(bh2[nb], bh_b + boff);
            }
            #pragma unroll
            for (int mi = 0; mi < 4; mi++) {
                uint32_t av[4];
                uint32_t aoff = (uint32_t)((wm + mi*16 + a_row) * (RS*2) + a_cb + ks*32);
                ldsm_x4(av, a_b + aoff);
                #pragma unroll
                for (int ni = 0; ni < 4; ni++) {
                    int nb = ni >> 1, hf = (ni & 1) * 2;
                    mma_f16(d[mi][ni], av, bh2[nb][hf], bh2[nb][hf+1]);
                }
            }
        }
        __syncthreads();
    }

    const int q  = lane >> 2;
    const int tq = lane & 3;
    #pragma unroll
    for (int mi = 0; mi < 4; mi++) {
        int row0 = by*128 + wm + mi*16 + q;
        #pragma unroll
        for (int ni = 0; ni < 4; ni++) {
            int col = bx*128 + wn + ni*8 + tq*2;
            size_t off0 = (size_t)row0 * N + col;
            size_t off1 = off0 + (size_t)8 * N;
            float v0 = d[mi][ni][0], v1 = d[mi][ni][1];
            float v2 = d[mi][ni][2], v3 = d[mi][ni][3];
            if (EPI == 1) {
                float2 x0 = *(const float2*)(X + off0);
                float2 x1 = *(const float2*)(X + off1);
                *(float2*)(Cf + off0) = make_float2(v0 + x0.x, v1 + x0.y);
                *(float2*)(Cf + off1) = make_float2(v2 + x1.x, v3 + x1.y);
            } else if (EPI == 2) {
                // bx tile == one head (HD == 128). X = freqs table (S, HD/2, 2).
                int head = bx;
                if (head < NH + NKV) {
                    int cl = wn + ni*8 + tq*2;
                    int r0 = row0, r1 = row0 + 8;
                    int b0 = r0 >> 11;
                    int s0 = r0 & (SEQ-1), s1 = r1 & (SEQ-1);
                    float2 f0 = *(const float2*)(X + (size_t)s0*HD + cl);
                    float2 f1 = *(const float2*)(X + (size_t)s1*HD + cl);
                    float n00 = v0*f0.x - v1*f0.y, n01 = v1*f0.x + v0*f0.y;
                    float n10 = v2*f1.x - v3*f1.y, n11 = v3*f1.x + v2*f1.y;
                    if (head < NH) {
                        size_t o0 = ((size_t)(b0*NH + head)*SEQ + s0)*HD + cl;
                        size_t o1 = ((size_t)(b0*NH + head)*SEQ + s1)*HD + cl;
                        store_h2g(Qo, o0, n00, n01);
                        store_h2g(Qo, o1, n10, n11);
                    } else {
                        int kh = head - NH;
                        size_t o0 = ((size_t)(b0*NKV + kh)*SEQ + s0)*HD + cl;
                        size_t o1 = ((size_t)(b0*NKV + kh)*SEQ + s1)*HD + cl;
                        store_h2g(Ko, o0, n00, n01);
                        store_h2g(Ko, o1, n10, n11);
                    }
                } else {
                    *(float2*)(Cf + off0) = make_float2(v0, v1);
                    *(float2*)(Cf + off1) = make_float2(v2, v3);
                }
            } else if (EPI == 3) {
                __half2 x0 = *(const __half2*)(Xh + off0);
                __half2 x1 = *(const __half2*)(Xh + off1);
                store_h2g(Ch, off0, v0 * silu_f(__half2float(x0.x)),
                                    v1 * silu_f(__half2float(x0.y)));
                store_h2g(Ch, off1, v2 * silu_f(__half2float(x1.x)),
                                    v3 * silu_f(__half2float(x1.y)));
            } else {  // EPI 5
                store_h2g(Ch, off0, v0, v1);
                store_h2g(Ch, off1, v2, v3);
            }
        }
    }
}

// ================= HMMA flash attention (fp16, causal, GQA) ====================
// Q,K,V,P all single fp16 products. Heavy tiles scheduled first (reversed bx).
#define AQ_RS   136
#define AV_RS   72
#define AQT_B   (128*AQ_RS*2)    // 34816
#define AKT_B   (64*AQ_RS*2)     // 17408
#define AVT_B   (128*AV_RS*2)    // 18432
#define ATTN_SMEM (AQT_B + AKT_B + AVT_B)   // 70656

__global__ __launch_bounds__(256, 2) void attn_hmma(
    const __half* __restrict__ Q, const __half* __restrict__ Kg,
    const __half* __restrict__ Vg, __half* __restrict__ Oh)
{
    extern __shared__ char smem[];
    uint32_t sb = smem_u32(smem);
    uint32_t q_s = sb;
    uint32_t k_s = sb + AQT_B;
    uint32_t v_s = k_s + AKT_B;

    const int tid = threadIdx.x, wid = tid >> 5, lane = tid & 31;
    const int bx = gridDim.x - 1 - blockIdx.x;   // heavy-first scheduling
    const int h = blockIdx.y, b = blockIdx.z;
    const int kvh = h >> 2;
    const int q0 = bx * 128;

    const __half* gQ = Q  + ((size_t)(b*NH + h) * SEQ + q0) * HD;
    const __half* gK = Kg + (size_t)(b*NKV + kvh) * SEQ * HD;
    const __half* gV = Vg + (size_t)(b*NKV + kvh) * HD * SEQ;

    #pragma unroll
    for (int i = 0; i < 8; i++) {
        int ch = i * 256 + tid;
        int r = ch >> 4, cc = ch & 15;
        uint32_t so = (uint32_t)(r * (AQ_RS*2) + cc * 16);
        cpa16(q_s + so, gQ + (size_t)r * HD + cc * 8);
    }
    asm volatile("cp.async.commit_group;\n" ::: "memory");

    float O[16][4];
    #pragma unroll
    for (int i = 0; i < 16; i++)
        #pragma unroll
        for (int j = 0; j < 4; j++) O[i][j] = 0.0f;
    float m0 = -1e30f, m1 = -1e30f, l0 = 0.0f, l1 = 0.0f;

    const int a_row = lane & 15;
    const int a_cb  = (lane >> 4) * 16;
    const int b_row = (lane & 7) | ((lane >> 1) & 8);
    const int b_cb  = ((lane >> 3) & 1) * 16;
    const int r0g = q0 + wid*16 + (lane >> 2);
    const int r1g = r0g + 8;
    const float scale = rsqrtf((float)EMBED);

    const int ktiles = 2*bx + 2;
    for (int kt = 0; kt < ktiles; kt++) {
        int k0 = kt * 64;
        __syncthreads();
        #pragma unroll
        for (int i = 0; i < 4; i++) {
            int ch = i * 256 + tid;
            int r = ch >> 4, cc = ch & 15;
            uint32_t so = (uint32_t)(r * (AQ_RS*2) + cc * 16);
            cpa16(k_s + so, gK + (size_t)(k0 + r) * HD + cc * 8);
        }
        #pragma unroll
        for (int i = 0; i < 4; i++) {
            int ch = i * 256 + tid;
            int r = ch >> 3, cc = ch & 7;
            uint32_t so = (uint32_t)(r * (AV_RS*2) + cc * 16);
            cpa16(v_s + so, gV + (size_t)r * SEQ + k0 + cc * 8);
        }
        asm volatile("cp.async.commit_group;\n" ::: "memory");
        asm volatile("cp.async.wait_group 0;\n" ::: "memory");
        __syncthreads();

        float S[8][4];
        #pragma unroll
        for (int i = 0; i < 8; i++)
            #pragma unroll
            for (int j = 0; j < 4; j++) S[i][j] = 0.0f;

        #pragma unroll
        for (int kk = 0; kk < 8; kk++) {
            uint32_t av[4];
            uint32_t aoff = (uint32_t)((wid*16 + a_row) * (AQ_RS*2) + a_cb + kk*32);
            ldsm_x4(av, q_s + aoff);
            #pragma unroll
            for (int np = 0; np < 4; np++) {
                uint32_t bv[4];
                uint32_t boff = (uint32_t)((np*16 + b_row) * (AQ_RS*2) + b_cb + kk*32);
                ldsm_x4(bv, k_s + boff);
                mma_f16(S[2*np],   av, bv[0], bv[1]);
                mma_f16(S[2*np+1], av, bv[2], bv[3]);
            }
        }

        #pragma unroll
        for (int ni = 0; ni < 8; ni++) {
            int c0 = k0 + ni*8 + 2*(lane & 3);
            S[ni][0] = (c0     > r0g) ? -1e30f : S[ni][0] * scale;
            S[ni][1] = (c0 + 1 > r0g) ? -1e30f : S[ni][1] * scale;
            S[ni][2] = (c0     > r1g) ? -1e30f : S[ni][2] * scale;
            S[ni][3] = (c0 + 1 > r1g) ? -1e30f : S[ni][3] * scale;
        }

        float mx0 = -1e30f, mx1 = -1e30f;
        #pragma unroll
        for (int ni = 0; ni < 8; ni++) {
            mx0 = fmaxf(mx0, fmaxf(S[ni][0], S[ni][1]));
            mx1 = fmaxf(mx1, fmaxf(S[ni][2], S[ni][3]));
        }
        mx0 = fmaxf(mx0, __shfl_xor_sync(0xffffffffu, mx0, 1));
        mx0 = fmaxf(mx0, __shfl_xor_sync(0xffffffffu, mx0, 2));
        mx1 = fmaxf(mx1, __shfl_xor_sync(0xffffffffu, mx1, 1));
        mx1 = fmaxf(mx1, __shfl_xor_sync(0xffffffffu, mx1, 2));
        float mn0 = fmaxf(m0, mx0), mn1 = fmaxf(m1, mx1);
        float corr0 = __expf(m0 - mn0), corr1 = __expf(m1 - mn1);
        m0 = mn0; m1 = mn1;

        uint32_t PH[8][2];
        float ls0 = 0.0f, ls1 = 0.0f;
        #pragma unroll
        for (int ni = 0; ni < 8; ni++) {
            float p0 = __expf(S[ni][0] - mn0);
            float p1 = __expf(S[ni][1] - mn0);
            float p2 = __expf(S[ni][2] - mn1);
            float p3 = __expf(S[ni][3] - mn1);
            ls0 += p0 + p1; ls1 += p2 + p3;
            PH[ni][0] = packh(p0, p1);
            PH[ni][1] = packh(p2, p3);
        }
        ls0 += __shfl_xor_sync(0xffffffffu, ls0, 1);
        ls0 += __shfl_xor_sync(0xffffffffu, ls0, 2);
        ls1 += __shfl_xor_sync(0xffffffffu, ls1, 1);
        ls1 += __shfl_xor_sync(0xffffffffu, ls1, 2);
        l0 = l0 * corr0 + ls0;
        l1 = l1 * corr1 + ls1;

        #pragma unroll
        for (int nb = 0; nb < 16; nb++) {
            O[nb][0] *= corr0; O[nb][1] *= corr0;
            O[nb][2] *= corr1; O[nb][3] *= corr1;
        }

        #pragma unroll
        for (int kc = 0; kc < 4; kc++) {
            uint32_t ah2[4] = {PH[2*kc][0], PH[2*kc][1], PH[2*kc+1][0], PH[2*kc+1][1]};
            #pragma unroll
            for (int dp = 0; dp < 8; dp++) {
                uint32_t bv[4];
                uint32_t boff = (uint32_t)((dp*16 + b_row) * (AV_RS*2) + b_cb + kc*32);
                ldsm_x4(bv, v_s + boff);
                mma_f16(O[2*dp],   ah2, bv[0], bv[1]);
                mma_f16(O[2*dp+1], ah2, bv[2], bv[3]);
            }
        }
    }

    float inv0 = 1.0f / l0, inv1 = 1.0f / l1;
    #pragma unroll
    for (int nb = 0; nb < 16; nb++) {
        int col = h*HD + nb*8 + 2*(lane & 3);
        size_t o0 = ((size_t)(b*SEQ) + r0g) * EMBED + col;
        size_t o1 = ((size_t)(b*SEQ) + r1g) * EMBED + col;
        store_h2g(Oh, o0, O[nb][0]*inv0, O[nb][1]*inv0);
        store_h2g(Oh, o1, O[nb][2]*inv1, O[nb][3]*inv1);
    }
}

// ================= launcher ====================================================
extern "C" void kernel_launch(void* const* d_in, const int* in_sizes, int n_in,
                              void* d_out, int out_size)
{
    const float* x      = (const float*)d_in[0];
    const float* freqs  = (const float*)d_in[2];
    const float* w_qkv  = (const float*)d_in[4];
    const float* w_fc   = (const float*)d_in[5];
    const float* w1     = (const float*)d_in[6];
    const float* w2     = (const float*)d_in[7];
    const float* w3     = (const float*)d_in[8];
    const float* attn_w = (const float*)d_in[9];
    const float* ff_w   = (const float*)d_in[10];
    float* out = (float*)d_out;

    float *qkv, *h2;
    __half *ff1h, *nbuf, *abuf, *fbuf, *qb, *kb, *vb;
    __half *wq, *wf, *w1b, *w2b, *w3b;
    cudaGetSymbolAddress((void**)&qkv,  g_qkv);
    cudaGetSymbolAddress((void**)&h2,   g_h2);
    cudaGetSymbolAddress((void**)&ff1h, g_ff1);
    cudaGetSymbolAddress((void**)&nbuf, g_n);
    cudaGetSymbolAddress((void**)&abuf, g_a);
    cudaGetSymbolAddress((void**)&fbuf, g_f);
    cudaGetSymbolAddress((void**)&qb,   g_q);
    cudaGetSymbolAddress((void**)&kb,   g_k);
    cudaGetSymbolAddress((void**)&vb,   g_v);
    cudaGetSymbolAddress((void**)&wq,   g_wqkv);
    cudaGetSymbolAddress((void**)&wf,   g_wfc);
    cudaGetSymbolAddress((void**)&w1b,  g_w1);
    cudaGetSymbolAddress((void**)&w2b,  g_w2);
    cudaGetSymbolAddress((void**)&w3b,  g_w3);

    cudaFuncSetAttribute((const void*)attn_hmma,
                         cudaFuncAttributeMaxDynamicSharedMemorySize, ATTN_SMEM);
    cudaFuncSetAttribute((const void*)hmma_gemm<1>,
                         cudaFuncAttributeMaxDynamicSharedMemorySize, GEMM_SMEM);
    cudaFuncSetAttribute((const void*)hmma_gemm<2>,
                         cudaFuncAttributeMaxDynamicSharedMemorySize, GEMM_SMEM);
    cudaFuncSetAttribute((const void*)hmma_gemm<3>,
                         cudaFuncAttributeMaxDynamicSharedMemorySize, GEMM_SMEM);
    cudaFuncSetAttribute((const void*)hmma_gemm<5>,
                         cudaFuncAttributeMaxDynamicSharedMemorySize, GEMM_SMEM);

    // weight fp16 conversion
    cvt_h<<<(QKV_N*EMBED/4 + 255)/256, 256>>>(w_qkv, wq, QKV_N*EMBED/4);
    cvt_h<<<(EMBED*EMBED/4 + 255)/256, 256>>>(w_fc, wf, EMBED*EMBED/4);
    cvt_h<<<(FF*EMBED/4 + 255)/256, 256>>>(w1, w1b, FF*EMBED/4);
    cvt_h<<<(FF*EMBED/4 + 255)/256, 256>>>(w2, w2b, FF*EMBED/4);
    cvt_h<<<(EMBED*FF/4 + 255)/256, 256>>>(w3, w3b, EMBED*FF/4);

    // 1) g = rmsnorm(x) -> fp16
    rmsnorm_h<<<ROWS, 256>>>(x, attn_w, nbuf);
    // 2) qkv GEMM with fused RoPE (Q,K fp16 head-major) ; V -> fp32 qkv
    hmma_gemm<2><<<dim3(QKV_N/128, ROWS/128), 256, GEMM_SMEM>>>(
        nbuf, wq, qkv, freqs, nullptr, nullptr, qb, kb, ROWS, QKV_N, EMBED);
    // 3) V transpose -> fp16
    v_split_t<<<dim3(SEQ/32, HD/32, BATCH*NKV), 256>>>(qkv, vb);
    // 4) attention -> fp16
    attn_hmma<<<dim3(SEQ/128, NH, BATCH), 256, ATTN_SMEM>>>(qb, kb, vb, abuf);
    // 5) h2 = x + attn @ w_fc^T
    hmma_gemm<1><<<dim3(EMBED/128, ROWS/128), 256, GEMM_SMEM>>>(
        abuf, wf, h2, x, nullptr, nullptr, nullptr, nullptr, ROWS, EMBED, EMBED);
    // 6) g2 = rmsnorm(h2) -> fp16
    rmsnorm_h<<<ROWS, 256>>>(h2, ff_w, nbuf);
    // 7) ff1 = g2 @ w1^T (fp16)
    hmma_gemm<5><<<dim3(FF/128, ROWS/128), 256, GEMM_SMEM>>>(
        nbuf, w1b, nullptr, nullptr, nullptr, ff1h, nullptr, nullptr, ROWS, FF, EMBED);
    // 8) ff = silu(ff1) * (g2 @ w2^T) -> fp16
    hmma_gemm<3><<<dim3(FF/128, ROWS/128), 256, GEMM_SMEM>>>(
        nbuf, w2b, nullptr, nullptr, ff1h, fbuf, nullptr, nullptr, ROWS, FF, EMBED);
    // 9) out = h2 + ff @ w3^T
    hmma_gemm<1><<<dim3(EMBED/128, ROWS/128), 256, GEMM_SMEM>>>(
        fbuf, w3b, out, h2, nullptr, nullptr, nullptr, nullptr, ROWS, EMBED, FF);
}